// round 11
// baseline (speedup 1.0000x reference)
#include <cuda_runtime.h>
#include <cuda_bf16.h>
#include <math.h>
#include <stdint.h>

// Problem constants
#define BB 2
#define TT 2048
#define DM 1024
#define NH 16
#define DH 64
#define BT (BB*TT)          // 4096
#define BH (BB*NH)          // 32

// Scratch (device globals; no allocation allowed)
__device__ float g_q[BH * TT * DH];     // [B,H,T,Dh] fp32 (pre-rope)
__device__ float g_k[BH * TT * DH];
__device__ float g_cosv[TT * 32];
__device__ float g_sinv[TT * 32];

// bf16 hi/lo split buffers
__device__ __nv_bfloat16 g_xhi[BT * DM];
__device__ __nv_bfloat16 g_xlo[BT * DM];
__device__ __nv_bfloat16 g_whi[4 * DM * DM];   // Wq,Wk,Wv,Wo
__device__ __nv_bfloat16 g_wlo[4 * DM * DM];
__device__ __nv_bfloat16 g_qhi[BH * TT * DH];  // roped, scaled by 0.125
__device__ __nv_bfloat16 g_qlo[BH * TT * DH];
__device__ __nv_bfloat16 g_khi[BH * TT * DH];  // roped
__device__ __nv_bfloat16 g_klo[BH * TT * DH];
__device__ __nv_bfloat16 g_vhi[BH * TT * DH];
__device__ __nv_bfloat16 g_vlo[BH * TT * DH];
__device__ __nv_bfloat16 g_ahi[BT * DM];       // attn output split [B,T,D]
__device__ __nv_bfloat16 g_alo[BT * DM];

// ---------------------------------------------------------------------------
// PTX helpers (plain sm_103 target: ldmatrix + mma.sync + cp.async)
// ---------------------------------------------------------------------------
__device__ __forceinline__ uint32_t smem_u32(const void* p) {
    uint32_t a;
    asm("{ .reg .u64 t; cvta.to.shared.u64 t, %1; cvt.u32.u64 %0, t; }"
        : "=r"(a) : "l"(p));
    return a;
}

__device__ __forceinline__ void ldsm_x4(uint32_t* r, uint32_t addr) {
    asm volatile("ldmatrix.sync.aligned.m8n8.x4.shared.b16 {%0,%1,%2,%3}, [%4];"
                 : "=r"(r[0]), "=r"(r[1]), "=r"(r[2]), "=r"(r[3]) : "r"(addr));
}

__device__ __forceinline__ void ldsm_x4_t(uint32_t* r, uint32_t addr) {
    asm volatile("ldmatrix.sync.aligned.m8n8.x4.trans.shared.b16 {%0,%1,%2,%3}, [%4];"
                 : "=r"(r[0]), "=r"(r[1]), "=r"(r[2]), "=r"(r[3]) : "r"(addr));
}

__device__ __forceinline__ void mma_bf16(float* d, const uint32_t* a,
                                         uint32_t b0, uint32_t b1) {
    asm volatile(
        "mma.sync.aligned.m16n8k16.row.col.f32.bf16.bf16.f32 "
        "{%0,%1,%2,%3}, {%4,%5,%6,%7}, {%8,%9}, {%0,%1,%2,%3};"
        : "+f"(d[0]), "+f"(d[1]), "+f"(d[2]), "+f"(d[3])
        : "r"(a[0]), "r"(a[1]), "r"(a[2]), "r"(a[3]), "r"(b0), "r"(b1));
}

__device__ __forceinline__ void cp16(uint32_t s, const void* g) {
    asm volatile("cp.async.cg.shared.global [%0], [%1], 16;" :: "r"(s), "l"(g));
}
__device__ __forceinline__ void cp_commit() {
    asm volatile("cp.async.commit_group;" ::: "memory");
}
__device__ __forceinline__ void cp_wait0() {
    asm volatile("cp.async.wait_group 0;" ::: "memory");
}

__device__ __forceinline__ uint32_t pack_bf16x2(float x, float y) {
    __nv_bfloat162 h = __floats2bfloat162_rn(x, y);
    return *(uint32_t*)&h;
}

// split a float pair into bf16 hi pair + bf16 lo (residual) pair
__device__ __forceinline__ void split2(float x, float y,
                                       uint32_t& hv, uint32_t& lv) {
    __nv_bfloat16 h0 = __float2bfloat16(x);
    __nv_bfloat16 h1 = __float2bfloat16(y);
    hv = ((uint32_t)*(uint16_t*)&h1 << 16) | *(uint16_t*)&h0;
    lv = pack_bf16x2(x - __bfloat162float(h0), y - __bfloat162float(h1));
}

// ---------------------------------------------------------------------------
// fp32 -> bf16 hi/lo split kernels (vectorized: 2 elements / thread)
// ---------------------------------------------------------------------------
__global__ __launch_bounds__(256)
void split2_kernel(const float* __restrict__ src,
                   __nv_bfloat16* __restrict__ hi,
                   __nv_bfloat16* __restrict__ lo, int n2)
{
    int idx = blockIdx.x * blockDim.x + threadIdx.x;
    if (idx >= n2) return;
    float2 v = ((const float2*)src)[idx];
    uint32_t hv, lv;
    split2(v.x, v.y, hv, lv);
    ((uint32_t*)hi)[idx] = hv;
    ((uint32_t*)lo)[idx] = lv;
}

__global__ __launch_bounds__(256)
void split_w2_kernel(const float* __restrict__ w0, const float* __restrict__ w1,
                     const float* __restrict__ w2, const float* __restrict__ w3)
{
    int idx = blockIdx.x * blockDim.x + threadIdx.x;   // 0 .. 2M-1 (pairs)
    int e = idx * 2;
    int w = e >> 20;
    int off = e & 0xFFFFF;
    const float* src = (w == 0) ? w0 : (w == 1) ? w1 : (w == 2) ? w2 : w3;
    float2 v = *(const float2*)(src + off);
    uint32_t hv, lv;
    split2(v.x, v.y, hv, lv);
    ((uint32_t*)g_whi)[idx] = hv;
    ((uint32_t*)g_wlo)[idx] = lv;
}

// ---------------------------------------------------------------------------
// mma.sync split-bf16 GEMM, cp.async 2-stage, single sync per K-chunk.
// CTA tile 128x128, K-chunk 32, 4 warps as 2(m) x 2(n); warp tile 64x64
// (big warp tile -> 1.5x less ldmatrix traffic per MMA).
// MODE 0: A = x split, W/bias by n>>10 (Wq/Wk/Wv).
//         w<2 -> fp32 g_q/g_k [B,H,T,Dh];  w==2 -> bf16 split g_vhi/g_vlo
// MODE 1: A = attn split, W = slot 3 (Wo), bias b0, out -> [M,1024] fp32
// ---------------------------------------------------------------------------
#define PADK 40   // bf16 per smem row (32 data + 8 pad); 80B stride
#define GARR (128 * PADK * 2)        // 10240 B per array
#define GSTG (4 * GARR)              // 40960 B per stage
#define GSMEM (2 * GSTG)             // 81920 B total

template <int MODE>
__global__ __launch_bounds__(128, 2)
void gemm_mma(const __nv_bfloat16* __restrict__ Ahi,
              const __nv_bfloat16* __restrict__ Alo,
              const float* __restrict__ b0, const float* __restrict__ b1,
              const float* __restrict__ b2, float* __restrict__ out)
{
    extern __shared__ char dsm[];
    const uint32_t sbase = smem_u32(dsm);

    const int tid = threadIdx.x;
    const int lane = tid & 31, wid = tid >> 5;
    const int m0 = blockIdx.y * 128;
    const int n_base = blockIdx.x * 128;
    const int w = (MODE == 0) ? (n_base >> 10) : 3;
    const int n_loc0 = (MODE == 0) ? (n_base & 1023) : n_base;
    const int warp_m = wid >> 1;   // 0..1 -> 64-row slice
    const int warp_n = wid & 1;    // 0..1 -> 64-col slice

    // global load mapping: 1 thread per row, 4 x 16B segments
    const __nv_bfloat16* pAh = Ahi + (size_t)(m0 + tid) * DM;
    const __nv_bfloat16* pAl = Alo + (size_t)(m0 + tid) * DM;
    const __nv_bfloat16* pWh = g_whi + ((size_t)w << 20) + (size_t)(n_loc0 + tid) * DM;
    const __nv_bfloat16* pWl = g_wlo + ((size_t)w << 20) + (size_t)(n_loc0 + tid) * DM;

    const uint32_t st_off = tid * (PADK * 2);

    const int j = lane >> 3, r = lane & 7;
    const int mA = (j & 1) * 8 + r;
    const int kA = (j >> 1) * 8;
    const int nB = (j >> 1) * 8 + r;
    const int kB = (j & 1) * 8;

    float acc[4][8][4];
    #pragma unroll
    for (int i = 0; i < 4; i++)
        #pragma unroll
        for (int t = 0; t < 8; t++)
            #pragma unroll
            for (int e = 0; e < 4; e++) acc[i][t][e] = 0.0f;

    auto PF = [&](int c, int s) {
        uint32_t b = sbase + s * GSTG + st_off;
        const char* a  = (const char*)(pAh + c * 32);
        const char* l  = (const char*)(pAl + c * 32);
        const char* h  = (const char*)(pWh + c * 32);
        const char* w2 = (const char*)(pWl + c * 32);
        #pragma unroll
        for (int s2 = 0; s2 < 4; s2++) {
            cp16(b + s2 * 16,            a + s2 * 16);
            cp16(b + GARR + s2 * 16,     l + s2 * 16);
            cp16(b + 2 * GARR + s2 * 16, h + s2 * 16);
            cp16(b + 3 * GARR + s2 * 16, w2 + s2 * 16);
        }
    };

    PF(0, 0); cp_commit();

    for (int c = 0; c < 32; c++) {
        const int cur = c & 1;
        cp_wait0();          // stage cur's data has arrived
        __syncthreads();     // publish stage cur; all reads of stage cur^1 done
        if (c + 1 < 32) { PF(c + 1, cur ^ 1); cp_commit(); }

        const uint32_t bAh = sbase + cur * GSTG;
        const uint32_t bAl = bAh + GARR;
        const uint32_t bWh = bAh + 2 * GARR;
        const uint32_t bWl = bAh + 3 * GARR;

        #pragma unroll
        for (int kk = 0; kk < 2; kk++) {
            uint32_t ah[4][4], al[4][4];
            #pragma unroll
            for (int i = 0; i < 4; i++) {
                uint32_t roff = (uint32_t)(warp_m * 64 + i * 16 + mA) * (PADK * 2)
                              + (uint32_t)(kk * 16 + kA) * 2;
                ldsm_x4(ah[i], bAh + roff);
                ldsm_x4(al[i], bAl + roff);
            }
            #pragma unroll
            for (int p = 0; p < 4; p++) {
                uint32_t roff = (uint32_t)(warp_n * 64 + p * 16 + nB) * (PADK * 2)
                              + (uint32_t)(kk * 16 + kB) * 2;
                uint32_t wh[4], wl[4];
                ldsm_x4(wh, bWh + roff);
                ldsm_x4(wl, bWl + roff);
                #pragma unroll
                for (int i = 0; i < 4; i++) {
                    mma_bf16(acc[i][2*p],   ah[i], wh[0], wh[1]);
                    mma_bf16(acc[i][2*p+1], ah[i], wh[2], wh[3]);
                    mma_bf16(acc[i][2*p],   ah[i], wl[0], wl[1]);
                    mma_bf16(acc[i][2*p+1], ah[i], wl[2], wl[3]);
                    mma_bf16(acc[i][2*p],   al[i], wh[0], wh[1]);
                    mma_bf16(acc[i][2*p+1], al[i], wh[2], wh[3]);
                }
            }
        }
    }

    const float* bias = (MODE == 0) ? ((w == 0) ? b0 : (w == 1) ? b1 : b2) : b0;
    const int gid = lane >> 2, tig2 = (lane & 3) * 2;

    #pragma unroll
    for (int i = 0; i < 4; i++) {
        const int mr0 = m0 + warp_m * 64 + i * 16 + gid;
        #pragma unroll
        for (int t = 0; t < 8; t++) {
            const int nl = n_loc0 + warp_n * 64 + (t >> 1) * 16 + (t & 1) * 8 + tig2;
            const float bx = bias[nl], by = bias[nl + 1];
            float2 v0 = make_float2(acc[i][t][0] + bx, acc[i][t][1] + by);
            float2 v1 = make_float2(acc[i][t][2] + bx, acc[i][t][3] + by);
            if (MODE == 0) {
                const int h = nl >> 6, dh = nl & 63;
                if (w == 2) {
                    #pragma unroll
                    for (int hv = 0; hv < 2; hv++) {
                        const int m_ = mr0 + hv * 8;
                        const int b_ = m_ >> 11, tt = m_ & 2047;
                        size_t e = (((size_t)(b_ * NH + h) * TT) + tt) * DH + dh;
                        float vx = hv ? v1.x : v0.x, vy = hv ? v1.y : v0.y;
                        uint32_t hb, lb;
                        split2(vx, vy, hb, lb);
                        *(uint32_t*)&g_vhi[e] = hb;
                        *(uint32_t*)&g_vlo[e] = lb;
                    }
                } else {
                    float* dst = (w == 0) ? g_q : g_k;
                    {
                        const int b_ = mr0 >> 11, tt = mr0 & 2047;
                        *(float2*)&dst[(((size_t)(b_ * NH + h) * TT) + tt) * DH + dh] = v0;
                    }
                    {
                        const int m2 = mr0 + 8;
                        const int b_ = m2 >> 11, tt = m2 & 2047;
                        *(float2*)&dst[(((size_t)(b_ * NH + h) * TT) + tt) * DH + dh] = v1;
                    }
                }
            } else {
                *(float2*)&out[(size_t)mr0 * DM + nl]       = v0;
                *(float2*)&out[(size_t)(mr0 + 8) * DM + nl] = v1;
            }
        }
    }
}

// ---------------------------------------------------------------------------
// RoPE: trig table (one FP64 eval per (t,i)), then parallel fp32 apply+split.
// ---------------------------------------------------------------------------
__global__ __launch_bounds__(256)
void trig_kernel()
{
    int idx = blockIdx.x * blockDim.x + threadIdx.x;   // 0 .. TT*32-1
    if (idx >= TT * 32) return;
    int i = idx & 31;
    int t = idx >> 5;
    double e   = -((double)(2 * i) / 64.0) * log(10000.0);
    float invf = (float)exp(e);
    float argf = (float)t * invf;
    double arg = (double)argf;
    g_cosv[idx] = (float)cos(arg);
    g_sinv[idx] = (float)sin(arg);
}

__global__ __launch_bounds__(256)
void rope_apply_kernel()
{
    int idx = blockIdx.x * blockDim.x + threadIdx.x;   // BH*TT*32
    int i  = idx & 31;
    int t  = (idx >> 5) & 2047;
    int bh = idx >> 16;
    float c = g_cosv[(t << 5) | i];
    float s = g_sinv[(t << 5) | i];

    size_t base = ((size_t)bh * TT + t) * DH;
    float q1 = g_q[base + i], q2 = g_q[base + i + 32];
    float rq1 = (q1 * c - q2 * s) * 0.125f;
    float rq2 = (q2 * c + q1 * s) * 0.125f;
    __nv_bfloat16 h;
    h = __float2bfloat16(rq1); g_qhi[base + i]      = h;
    g_qlo[base + i]      = __float2bfloat16(rq1 - __bfloat162float(h));
    h = __float2bfloat16(rq2); g_qhi[base + i + 32] = h;
    g_qlo[base + i + 32] = __float2bfloat16(rq2 - __bfloat162float(h));

    float k1 = g_k[base + i], k2 = g_k[base + i + 32];
    float rk1 = k1 * c - k2 * s;
    float rk2 = k2 * c + k1 * s;
    h = __float2bfloat16(rk1); g_khi[base + i]      = h;
    g_klo[base + i]      = __float2bfloat16(rk1 - __bfloat162float(h));
    h = __float2bfloat16(rk2); g_khi[base + i + 32] = h;
    g_klo[base + i + 32] = __float2bfloat16(rk2 - __bfloat162float(h));
}

// ---------------------------------------------------------------------------
// Flash attention on mma.sync, cp.async 2-stage, single sync per K/V tile.
// Block: 128 threads (4 warps), 128 q-rows; warp owns 32 q-rows (i=0..1)
// -> K/V fragments amortized over 2x the MMAs vs 16-row warps.
// Q fragments loaded directly from gmem into registers (one-time).
// ---------------------------------------------------------------------------
#define ASTR 72   // bf16 per smem row (64 data + 8 pad); 144B stride
#define AARR (64 * ASTR * 2)         // 9216 B per array
#define ASTG (4 * AARR)              // 36864 B per stage
#define ASMEM (2 * ASTG)             // 73728 B total

__global__ __launch_bounds__(128)
void attn_mma_kernel()
{
    extern __shared__ char dsm[];
    const uint32_t sbase = smem_u32(dsm);

    const int bh = blockIdx.y;
    const int q0 = blockIdx.x * 128;
    const int tid = threadIdx.x;
    const int lane = tid & 31, wid = tid >> 5;
    const int j = lane >> 3, r = lane & 7;
    const int gid = lane >> 2, tg2 = (lane & 3) * 2;

    const size_t headoff = (size_t)bh * TT * DH;
    const __nv_bfloat16* pQh = g_qhi + headoff + (size_t)q0 * DH;
    const __nv_bfloat16* pQl = g_qlo + headoff + (size_t)q0 * DH;
    const __nv_bfloat16* pKh = g_khi + headoff;
    const __nv_bfloat16* pKl = g_klo + headoff;
    const __nv_bfloat16* pVh = g_vhi + headoff;
    const __nv_bfloat16* pVl = g_vlo + headoff;

    // K/V tile-load mapping: 2 threads per row, 32 bf16 (64B) each
    const int lrow = tid >> 1, lhalf = (tid & 1) * 32;
    const uint32_t sm_off = lrow * (ASTR * 2) + lhalf * 2;

    auto PF = [&](int itj, int s) {     // K/V tile j0 = itj*64 -> stage s
        uint32_t b = sbase + s * ASTG + sm_off;
        const char* a = (const char*)(pKh + (size_t)(itj * 64 + lrow) * DH + lhalf);
        const char* c = (const char*)(pKl + (size_t)(itj * 64 + lrow) * DH + lhalf);
        const char* d = (const char*)(pVh + (size_t)(itj * 64 + lrow) * DH + lhalf);
        const char* e = (const char*)(pVl + (size_t)(itj * 64 + lrow) * DH + lhalf);
        #pragma unroll
        for (int s2 = 0; s2 < 4; s2++) {
            cp16(b + s2 * 16,            a + s2 * 16);
            cp16(b + AARR + s2 * 16,     c + s2 * 16);
            cp16(b + 2 * AARR + s2 * 16, d + s2 * 16);
            cp16(b + 3 * AARR + s2 * 16, e + s2 * 16);
        }
    };

    PF(0, 0); cp_commit();

    // ---- Q fragments straight from gmem (A-frag layout m16k16) ----
    uint32_t qh[2][4][4], ql[2][4][4];
    #pragma unroll
    for (int i = 0; i < 2; i++) {
        #pragma unroll
        for (int kk = 0; kk < 4; kk++) {
            #pragma unroll
            for (int rg = 0; rg < 4; rg++) {
                int m = wid * 32 + i * 16 + gid + (rg & 1) * 8;
                int kcol = kk * 16 + tg2 + (rg >> 1) * 8;
                qh[i][kk][rg] = *(const uint32_t*)(pQh + (size_t)m * DH + kcol);
                ql[i][kk][rg] = *(const uint32_t*)(pQl + (size_t)m * DH + kcol);
            }
        }
    }

    const int nB = (j >> 1) * 8 + r, kB = (j & 1) * 8;   // K ldsm lanes
    const int vk = lane & 15, vn8 = (lane >> 4) * 8;     // V trans lanes

    float m_r[2][2] = {{-INFINITY, -INFINITY}, {-INFINITY, -INFINITY}};
    float l_r[2][2] = {{0.0f, 0.0f}, {0.0f, 0.0f}};
    float oacc[2][8][4];
    #pragma unroll
    for (int i = 0; i < 2; i++)
        #pragma unroll
        for (int t = 0; t < 8; t++)
            #pragma unroll
            for (int e = 0; e < 4; e++) oacc[i][t][e] = 0.0f;

    for (int it = 0; it < 32; it++) {
        const int cur = it & 1;
        cp_wait0();
        __syncthreads();
        if (it + 1 < 32) { PF(it + 1, cur ^ 1); cp_commit(); }

        const uint32_t bKh = sbase + cur * ASTG;
        const uint32_t bKl = bKh + AARR;
        const uint32_t bVh = bKh + 2 * AARR;
        const uint32_t bVl = bKh + 3 * AARR;

        // ---- S = Q K^T (3 split combos) ----
        float sacc[2][8][4];
        #pragma unroll
        for (int i = 0; i < 2; i++)
            #pragma unroll
            for (int t = 0; t < 8; t++)
                #pragma unroll
                for (int e = 0; e < 4; e++) sacc[i][t][e] = 0.0f;

        #pragma unroll
        for (int kk = 0; kk < 4; kk++) {
            #pragma unroll
            for (int p = 0; p < 4; p++) {
                uint32_t off = (uint32_t)(p * 16 + nB) * (ASTR * 2)
                             + (uint32_t)(kk * 16 + kB) * 2;
                uint32_t kh4[4], kl4[4];
                ldsm_x4(kh4, bKh + off);
                ldsm_x4(kl4, bKl + off);
                #pragma unroll
                for (int i = 0; i < 2; i++) {
                    mma_bf16(sacc[i][2*p],   qh[i][kk], kh4[0], kh4[1]);
                    mma_bf16(sacc[i][2*p+1], qh[i][kk], kh4[2], kh4[3]);
                    mma_bf16(sacc[i][2*p],   qh[i][kk], kl4[0], kl4[1]);
                    mma_bf16(sacc[i][2*p+1], qh[i][kk], kl4[2], kl4[3]);
                    mma_bf16(sacc[i][2*p],   ql[i][kk], kh4[0], kh4[1]);
                    mma_bf16(sacc[i][2*p+1], ql[i][kk], kh4[2], kh4[3]);
                }
            }
        }

        // ---- online softmax per i (rows gid, gid+8 within each m16) ----
        #pragma unroll
        for (int i = 0; i < 2; i++) {
            float mx0 = -INFINITY, mx1 = -INFINITY;
            #pragma unroll
            for (int t = 0; t < 8; t++) {
                mx0 = fmaxf(mx0, fmaxf(sacc[i][t][0], sacc[i][t][1]));
                mx1 = fmaxf(mx1, fmaxf(sacc[i][t][2], sacc[i][t][3]));
            }
            #pragma unroll
            for (int off = 1; off < 4; off <<= 1) {
                mx0 = fmaxf(mx0, __shfl_xor_sync(0xffffffffu, mx0, off));
                mx1 = fmaxf(mx1, __shfl_xor_sync(0xffffffffu, mx1, off));
            }
            float mn0 = fmaxf(m_r[i][0], mx0), mn1 = fmaxf(m_r[i][1], mx1);
            float cr0 = __expf(m_r[i][0] - mn0), cr1 = __expf(m_r[i][1] - mn1);
            float rs0 = 0.0f, rs1 = 0.0f;
            #pragma unroll
            for (int t = 0; t < 8; t++) {
                sacc[i][t][0] = __expf(sacc[i][t][0] - mn0);
                sacc[i][t][1] = __expf(sacc[i][t][1] - mn0);
                sacc[i][t][2] = __expf(sacc[i][t][2] - mn1);
                sacc[i][t][3] = __expf(sacc[i][t][3] - mn1);
                rs0 += sacc[i][t][0] + sacc[i][t][1];
                rs1 += sacc[i][t][2] + sacc[i][t][3];
            }
            #pragma unroll
            for (int off = 1; off < 4; off <<= 1) {
                rs0 += __shfl_xor_sync(0xffffffffu, rs0, off);
                rs1 += __shfl_xor_sync(0xffffffffu, rs1, off);
            }
            l_r[i][0] = l_r[i][0] * cr0 + rs0;  m_r[i][0] = mn0;
            l_r[i][1] = l_r[i][1] * cr1 + rs1;  m_r[i][1] = mn1;
            #pragma unroll
            for (int t = 0; t < 8; t++) {
                oacc[i][t][0] *= cr0;  oacc[i][t][1] *= cr0;
                oacc[i][t][2] *= cr1;  oacc[i][t][3] *= cr1;
            }
        }

        // ---- O += P V (P split in regs, V split via ldmatrix.trans) ----
        #pragma unroll
        for (int kc = 0; kc < 4; kc++) {
            uint32_t phi[2][4], plo[2][4];
            #pragma unroll
            for (int i = 0; i < 2; i++) {
                split2(sacc[i][2*kc][0],   sacc[i][2*kc][1],   phi[i][0], plo[i][0]);
                split2(sacc[i][2*kc][2],   sacc[i][2*kc][3],   phi[i][1], plo[i][1]);
                split2(sacc[i][2*kc+1][0], sacc[i][2*kc+1][1], phi[i][2], plo[i][2]);
                split2(sacc[i][2*kc+1][2], sacc[i][2*kc+1][3], phi[i][3], plo[i][3]);
            }
            #pragma unroll
            for (int p = 0; p < 4; p++) {
                uint32_t off = (uint32_t)(kc * 16 + vk) * (ASTR * 2)
                             + (uint32_t)(p * 16 + vn8) * 2;
                uint32_t vh4[4], vl4[4];
                ldsm_x4_t(vh4, bVh + off);
                ldsm_x4_t(vl4, bVl + off);
                #pragma unroll
                for (int i = 0; i < 2; i++) {
                    mma_bf16(oacc[i][2*p],   phi[i], vh4[0], vh4[1]);
                    mma_bf16(oacc[i][2*p+1], phi[i], vh4[2], vh4[3]);
                    mma_bf16(oacc[i][2*p],   phi[i], vl4[0], vl4[1]);
                    mma_bf16(oacc[i][2*p+1], phi[i], vl4[2], vl4[3]);
                    mma_bf16(oacc[i][2*p],   plo[i], vh4[0], vh4[1]);
                    mma_bf16(oacc[i][2*p+1], plo[i], vh4[2], vh4[3]);
                }
            }
        }
    }

    // ---- epilogue: normalize, split to bf16 hi/lo, write [B,T,D] ----
    const int b_ = bh >> 4, h = bh & 15;
    uint32_t* ahi32 = (uint32_t*)g_ahi;
    uint32_t* alo32 = (uint32_t*)g_alo;

    #pragma unroll
    for (int i = 0; i < 2; i++) {
        const float inv0 = 1.0f / l_r[i][0], inv1 = 1.0f / l_r[i][1];
        const int row0 = q0 + wid * 32 + i * 16 + gid;
        #pragma unroll
        for (int t = 0; t < 8; t++) {
            const int col = h * 64 + t * 8 + tg2;
            uint32_t hv, lv;
            split2(oacc[i][t][0] * inv0, oacc[i][t][1] * inv0, hv, lv);
            size_t e0 = (((size_t)(b_ * TT + row0)) * DM + col) >> 1;
            ahi32[e0] = hv;  alo32[e0] = lv;
            split2(oacc[i][t][2] * inv1, oacc[i][t][3] * inv1, hv, lv);
            size_t e1 = (((size_t)(b_ * TT + row0 + 8)) * DM + col) >> 1;
            ahi32[e1] = hv;  alo32[e1] = lv;
        }
    }
}

// ---------------------------------------------------------------------------
extern "C" void kernel_launch(void* const* d_in, const int* in_sizes, int n_in,
                              void* d_out, int out_size)
{
    const float* x  = (const float*)d_in[0];
    const float* Wq = (const float*)d_in[1];
    const float* bq = (const float*)d_in[2];
    const float* Wk = (const float*)d_in[3];
    const float* bk = (const float*)d_in[4];
    const float* Wv = (const float*)d_in[5];
    const float* bv = (const float*)d_in[6];
    const float* Wo = (const float*)d_in[7];
    const float* bo = (const float*)d_in[8];
    float* out = (float*)d_out;

    cudaFuncSetAttribute(gemm_mma<0>, cudaFuncAttributeMaxDynamicSharedMemorySize, GSMEM);
    cudaFuncSetAttribute(gemm_mma<1>, cudaFuncAttributeMaxDynamicSharedMemorySize, GSMEM);
    cudaFuncSetAttribute(attn_mma_kernel, cudaFuncAttributeMaxDynamicSharedMemorySize, ASMEM);

    __nv_bfloat16 *xhi, *xlo, *ahi, *alo;
    cudaGetSymbolAddress((void**)&xhi, g_xhi);
    cudaGetSymbolAddress((void**)&xlo, g_xlo);
    cudaGetSymbolAddress((void**)&ahi, g_ahi);
    cudaGetSymbolAddress((void**)&alo, g_alo);

    // 0) split x and weights into bf16 hi/lo (vectorized) + trig table
    split2_kernel<<<(BT * DM / 2 + 255) / 256, 256>>>(x, xhi, xlo, BT * DM / 2);
    split_w2_kernel<<<(4 * DM * DM / 2 + 255) / 256, 256>>>(Wq, Wk, Wv, Wo);
    trig_kernel<<<(TT * 32 + 255) / 256, 256>>>();

    // 1) QKV projection: q,k -> fp32 [B,H,T,Dh]; v -> bf16 split
    dim3 g1(3072 / 128, BT / 128);
    gemm_mma<0><<<g1, 128, GSMEM>>>(xhi, xlo, bq, bk, bv, nullptr);

    // 2) RoPE apply + scale + bf16 split for q,k
    rope_apply_kernel<<<(BH * TT * 32) / 256, 256>>>();

    // 3) flash attention (mma.sync + cp.async) -> g_ahi/g_alo [B,T,D]
    dim3 g3(TT / 128, BH);
    attn_mma_kernel<<<g3, 128, ASMEM>>>();

    // 4) output projection -> d_out
    dim3 g4(DM / 128, BT / 128);
    gemm_mma<1><<<g4, 128, GSMEM>>>(ahi, alo, bo, nullptr, nullptr, out);
}

// round 12
// speedup vs baseline: 1.1378x; 1.1378x over previous
#include <cuda_runtime.h>
#include <cuda_bf16.h>
#include <math.h>
#include <stdint.h>

// Problem constants
#define BB 2
#define TT 2048
#define DM 1024
#define NH 16
#define DH 64
#define BT (BB*TT)          // 4096
#define BH (BB*NH)          // 32

// Scratch (device globals; no allocation allowed)
__device__ float g_cosv[TT * 32];
__device__ float g_sinv[TT * 32];

// bf16 hi/lo split buffers
__device__ __nv_bfloat16 g_xhi[BT * DM];
__device__ __nv_bfloat16 g_xlo[BT * DM];
__device__ __nv_bfloat16 g_whi[4 * DM * DM];   // Wq,Wk,Wv,Wo
__device__ __nv_bfloat16 g_wlo[4 * DM * DM];
__device__ __nv_bfloat16 g_qhi[BH * TT * DH];  // roped, scaled by 0.125
__device__ __nv_bfloat16 g_qlo[BH * TT * DH];
__device__ __nv_bfloat16 g_khi[BH * TT * DH];  // roped
__device__ __nv_bfloat16 g_klo[BH * TT * DH];
__device__ __nv_bfloat16 g_vhi[BH * TT * DH];
__device__ __nv_bfloat16 g_vlo[BH * TT * DH];
__device__ __nv_bfloat16 g_ahi[BT * DM];       // attn output split [B,T,D]
__device__ __nv_bfloat16 g_alo[BT * DM];

// ---------------------------------------------------------------------------
// PTX helpers (plain sm_103 target: ldmatrix + mma.sync + cp.async)
// ---------------------------------------------------------------------------
__device__ __forceinline__ uint32_t smem_u32(const void* p) {
    uint32_t a;
    asm("{ .reg .u64 t; cvta.to.shared.u64 t, %1; cvt.u32.u64 %0, t; }"
        : "=r"(a) : "l"(p));
    return a;
}

__device__ __forceinline__ void ldsm_x4(uint32_t* r, uint32_t addr) {
    asm volatile("ldmatrix.sync.aligned.m8n8.x4.shared.b16 {%0,%1,%2,%3}, [%4];"
                 : "=r"(r[0]), "=r"(r[1]), "=r"(r[2]), "=r"(r[3]) : "r"(addr));
}

__device__ __forceinline__ void ldsm_x4_t(uint32_t* r, uint32_t addr) {
    asm volatile("ldmatrix.sync.aligned.m8n8.x4.trans.shared.b16 {%0,%1,%2,%3}, [%4];"
                 : "=r"(r[0]), "=r"(r[1]), "=r"(r[2]), "=r"(r[3]) : "r"(addr));
}

__device__ __forceinline__ void mma_bf16(float* d, const uint32_t* a,
                                         uint32_t b0, uint32_t b1) {
    asm volatile(
        "mma.sync.aligned.m16n8k16.row.col.f32.bf16.bf16.f32 "
        "{%0,%1,%2,%3}, {%4,%5,%6,%7}, {%8,%9}, {%0,%1,%2,%3};"
        : "+f"(d[0]), "+f"(d[1]), "+f"(d[2]), "+f"(d[3])
        : "r"(a[0]), "r"(a[1]), "r"(a[2]), "r"(a[3]), "r"(b0), "r"(b1));
}

__device__ __forceinline__ void cp16(uint32_t s, const void* g) {
    asm volatile("cp.async.cg.shared.global [%0], [%1], 16;" :: "r"(s), "l"(g));
}
__device__ __forceinline__ void cp_commit() {
    asm volatile("cp.async.commit_group;" ::: "memory");
}
__device__ __forceinline__ void cp_wait0() {
    asm volatile("cp.async.wait_group 0;" ::: "memory");
}

__device__ __forceinline__ uint32_t pack_bf16x2(float x, float y) {
    __nv_bfloat162 h = __floats2bfloat162_rn(x, y);
    return *(uint32_t*)&h;
}

// split a float pair into bf16 hi pair + bf16 lo (residual) pair
__device__ __forceinline__ void split2(float x, float y,
                                       uint32_t& hv, uint32_t& lv) {
    __nv_bfloat16 h0 = __float2bfloat16(x);
    __nv_bfloat16 h1 = __float2bfloat16(y);
    hv = ((uint32_t)*(uint16_t*)&h1 << 16) | *(uint16_t*)&h0;
    lv = pack_bf16x2(x - __bfloat162float(h0), y - __bfloat162float(h1));
}

// ---------------------------------------------------------------------------
// fp32 -> bf16 hi/lo split kernels (vectorized: 2 elements / thread)
// ---------------------------------------------------------------------------
__global__ __launch_bounds__(256)
void split2_kernel(const float* __restrict__ src,
                   __nv_bfloat16* __restrict__ hi,
                   __nv_bfloat16* __restrict__ lo, int n2)
{
    int idx = blockIdx.x * blockDim.x + threadIdx.x;
    if (idx >= n2) return;
    float2 v = ((const float2*)src)[idx];
    uint32_t hv, lv;
    split2(v.x, v.y, hv, lv);
    ((uint32_t*)hi)[idx] = hv;
    ((uint32_t*)lo)[idx] = lv;
}

__global__ __launch_bounds__(256)
void split_w2_kernel(const float* __restrict__ w0, const float* __restrict__ w1,
                     const float* __restrict__ w2, const float* __restrict__ w3)
{
    int idx = blockIdx.x * blockDim.x + threadIdx.x;   // 0 .. 2M-1 (pairs)
    int e = idx * 2;
    int w = e >> 20;
    int off = e & 0xFFFFF;
    const float* src = (w == 0) ? w0 : (w == 1) ? w1 : (w == 2) ? w2 : w3;
    float2 v = *(const float2*)(src + off);
    uint32_t hv, lv;
    split2(v.x, v.y, hv, lv);
    ((uint32_t*)g_whi)[idx] = hv;
    ((uint32_t*)g_wlo)[idx] = lv;
}

// ---------------------------------------------------------------------------
// RoPE trig table: one FP64 eval per (t,i).
// Matches JAX fp32 rounding: arg = fp32(t)*fp32(inv_freq); trig in double.
// ---------------------------------------------------------------------------
__global__ __launch_bounds__(256)
void trig_kernel()
{
    int idx = blockIdx.x * blockDim.x + threadIdx.x;   // 0 .. TT*32-1
    if (idx >= TT * 32) return;
    int i = idx & 31;
    int t = idx >> 5;
    double e   = -((double)(2 * i) / 64.0) * log(10000.0);
    float invf = (float)exp(e);
    float argf = (float)t * invf;
    double arg = (double)argf;
    g_cosv[idx] = (float)cos(arg);
    g_sinv[idx] = (float)sin(arg);
}

// ---------------------------------------------------------------------------
// mma.sync split-bf16 GEMM (R9 config: 256 thr, 8 warps 4(m)x2(n), warp 32x64,
// cp.async 2-stage, single sync per K-chunk).
// MODE 0: A = x split, W/bias by n>>10 (Wq/Wk/Wv).
//         w<2 -> RoPE fused in epilogue -> bf16 split g_q*/g_k* [B,H,T,Dh]
//         w==2 -> bf16 split g_vhi/g_vlo
// MODE 1: A = attn split, W = slot 3 (Wo), bias b0, out -> [M,1024] fp32
// ---------------------------------------------------------------------------
#define PADK 40   // bf16 per smem row (32 data + 8 pad); 80B stride
#define GARR (128 * PADK * 2)        // 10240 B per array
#define GSTG (4 * GARR)              // 40960 B per stage
#define GSMEM (2 * GSTG)             // 81920 B total

template <int MODE>
__global__ __launch_bounds__(256, 2)
void gemm_mma(const __nv_bfloat16* __restrict__ Ahi,
              const __nv_bfloat16* __restrict__ Alo,
              const float* __restrict__ b0, const float* __restrict__ b1,
              const float* __restrict__ b2, float* __restrict__ out)
{
    extern __shared__ char dsm[];
    const uint32_t sbase = smem_u32(dsm);

    const int tid = threadIdx.x;
    const int lane = tid & 31, wid = tid >> 5;
    const int m0 = blockIdx.y * 128;
    const int n_base = blockIdx.x * 128;
    const int w = (MODE == 0) ? (n_base >> 10) : 3;
    const int n_loc0 = (MODE == 0) ? (n_base & 1023) : n_base;
    const int warp_m = wid >> 1;   // 0..3 -> 32-row slice
    const int warp_n = wid & 1;    // 0..1 -> 64-col slice

    const int lrow = tid >> 1;
    const int lseg = (tid & 1) * 16;
    const __nv_bfloat16* pAh = Ahi + (size_t)(m0 + lrow) * DM + lseg;
    const __nv_bfloat16* pAl = Alo + (size_t)(m0 + lrow) * DM + lseg;
    const __nv_bfloat16* pWh = g_whi + ((size_t)w << 20) + (size_t)(n_loc0 + lrow) * DM + lseg;
    const __nv_bfloat16* pWl = g_wlo + ((size_t)w << 20) + (size_t)(n_loc0 + lrow) * DM + lseg;

    const uint32_t st_off = lrow * (PADK * 2) + lseg * 2;

    const int j = lane >> 3, r = lane & 7;
    const int mA = (j & 1) * 8 + r;
    const int kA = (j >> 1) * 8;
    const int nB = (j >> 1) * 8 + r;
    const int kB = (j & 1) * 8;

    float acc[2][8][4];
    #pragma unroll
    for (int i = 0; i < 2; i++)
        #pragma unroll
        for (int t = 0; t < 8; t++)
            #pragma unroll
            for (int e = 0; e < 4; e++) acc[i][t][e] = 0.0f;

    auto PF = [&](int c, int s) {
        uint32_t b = sbase + s * GSTG + st_off;
        const char* a  = (const char*)(pAh + c * 32);
        const char* l  = (const char*)(pAl + c * 32);
        const char* h  = (const char*)(pWh + c * 32);
        const char* w2 = (const char*)(pWl + c * 32);
        cp16(b,                  a);   cp16(b + 16,              a + 16);
        cp16(b + GARR,           l);   cp16(b + GARR + 16,       l + 16);
        cp16(b + 2 * GARR,       h);   cp16(b + 2 * GARR + 16,   h + 16);
        cp16(b + 3 * GARR,       w2);  cp16(b + 3 * GARR + 16,   w2 + 16);
    };

    PF(0, 0); cp_commit();

    for (int c = 0; c < 32; c++) {
        const int cur = c & 1;
        cp_wait0();          // stage cur's data has arrived
        __syncthreads();     // publish stage cur; all reads of stage cur^1 done
        if (c + 1 < 32) { PF(c + 1, cur ^ 1); cp_commit(); }

        const uint32_t bAh = sbase + cur * GSTG;
        const uint32_t bAl = bAh + GARR;
        const uint32_t bWh = bAh + 2 * GARR;
        const uint32_t bWl = bAh + 3 * GARR;

        #pragma unroll
        for (int kk = 0; kk < 2; kk++) {
            uint32_t ah[2][4], al[2][4];
            #pragma unroll
            for (int i = 0; i < 2; i++) {
                uint32_t roff = (uint32_t)(warp_m * 32 + i * 16 + mA) * (PADK * 2)
                              + (uint32_t)(kk * 16 + kA) * 2;
                ldsm_x4(ah[i], bAh + roff);
                ldsm_x4(al[i], bAl + roff);
            }
            #pragma unroll
            for (int p = 0; p < 4; p++) {
                uint32_t roff = (uint32_t)(warp_n * 64 + p * 16 + nB) * (PADK * 2)
                              + (uint32_t)(kk * 16 + kB) * 2;
                uint32_t wh[4], wl[4];
                ldsm_x4(wh, bWh + roff);
                ldsm_x4(wl, bWl + roff);
                #pragma unroll
                for (int i = 0; i < 2; i++) {
                    mma_bf16(acc[i][2*p],   ah[i], wh[0], wh[1]);
                    mma_bf16(acc[i][2*p+1], ah[i], wh[2], wh[3]);
                    mma_bf16(acc[i][2*p],   ah[i], wl[0], wl[1]);
                    mma_bf16(acc[i][2*p+1], ah[i], wl[2], wl[3]);
                    mma_bf16(acc[i][2*p],   al[i], wh[0], wh[1]);
                    mma_bf16(acc[i][2*p+1], al[i], wh[2], wh[3]);
                }
            }
        }
    }

    const float* bias = (MODE == 0) ? ((w == 0) ? b0 : (w == 1) ? b1 : b2) : b0;
    const int gid = lane >> 2, tig2 = (lane & 3) * 2;

    if (MODE == 0 && w < 2) {
        // ---- fused RoPE epilogue: acc[i][t] (cols dh) pairs with acc[i][t+4]
        // (cols dh+32), same rows.  q additionally scaled by 1/8. ----
        const float scl = (w == 0) ? 0.125f : 1.0f;
        __nv_bfloat16* dhi = (w == 0) ? g_qhi : g_khi;
        __nv_bfloat16* dlo = (w == 0) ? g_qlo : g_klo;
        const int h = (n_loc0 + warp_n * 64) >> 6;

        #pragma unroll
        for (int i = 0; i < 2; i++) {
            const int mr0 = m0 + warp_m * 32 + i * 16 + gid;
            #pragma unroll
            for (int t = 0; t < 4; t++) {
                const int dh = t * 8 + tig2;              // 0..30
                const int nl1 = n_loc0 + warp_n * 64 + dh;
                const float bx1 = bias[nl1],      by1 = bias[nl1 + 1];
                const float bx2 = bias[nl1 + 32], by2 = bias[nl1 + 33];
                #pragma unroll
                for (int rs = 0; rs < 2; rs++) {
                    const int m_ = mr0 + rs * 8;
                    const int b_ = m_ >> 11, tt = m_ & 2047;
                    const float c0 = g_cosv[tt * 32 + dh];
                    const float s0 = g_sinv[tt * 32 + dh];
                    const float c1 = g_cosv[tt * 32 + dh + 1];
                    const float s1 = g_sinv[tt * 32 + dh + 1];
                    const float q1a = acc[i][t][rs*2+0]     + bx1;
                    const float q1b = acc[i][t][rs*2+1]     + by1;
                    const float q2a = acc[i][t+4][rs*2+0]   + bx2;
                    const float q2b = acc[i][t+4][rs*2+1]   + by2;
                    const float r1a = (q1a * c0 - q2a * s0) * scl;
                    const float r2a = (q2a * c0 + q1a * s0) * scl;
                    const float r1b = (q1b * c1 - q2b * s1) * scl;
                    const float r2b = (q2b * c1 + q1b * s1) * scl;
                    size_t base = (((size_t)(b_ * NH + h) * TT) + tt) * DH;
                    uint32_t hv, lv;
                    split2(r1a, r1b, hv, lv);
                    *(uint32_t*)&dhi[base + dh]      = hv;
                    *(uint32_t*)&dlo[base + dh]      = lv;
                    split2(r2a, r2b, hv, lv);
                    *(uint32_t*)&dhi[base + dh + 32] = hv;
                    *(uint32_t*)&dlo[base + dh + 32] = lv;
                }
            }
        }
    } else {
        #pragma unroll
        for (int i = 0; i < 2; i++) {
            const int mr0 = m0 + warp_m * 32 + i * 16 + gid;
            #pragma unroll
            for (int t = 0; t < 8; t++) {
                const int nl = n_loc0 + warp_n * 64 + t * 8 + tig2;
                const float bx = bias[nl], by = bias[nl + 1];
                float2 v0 = make_float2(acc[i][t][0] + bx, acc[i][t][1] + by);
                float2 v1 = make_float2(acc[i][t][2] + bx, acc[i][t][3] + by);
                if (MODE == 0) {
                    // w == 2: V -> bf16 split
                    const int h = nl >> 6, dh = nl & 63;
                    #pragma unroll
                    for (int hv_ = 0; hv_ < 2; hv_++) {
                        const int m_ = mr0 + hv_ * 8;
                        const int b_ = m_ >> 11, tt = m_ & 2047;
                        size_t e = (((size_t)(b_ * NH + h) * TT) + tt) * DH + dh;
                        float vx = hv_ ? v1.x : v0.x, vy = hv_ ? v1.y : v0.y;
                        uint32_t hb, lb;
                        split2(vx, vy, hb, lb);
                        *(uint32_t*)&g_vhi[e] = hb;
                        *(uint32_t*)&g_vlo[e] = lb;
                    }
                } else {
                    *(float2*)&out[(size_t)mr0 * DM + nl]       = v0;
                    *(float2*)&out[(size_t)(mr0 + 8) * DM + nl] = v1;
                }
            }
        }
    }
}

// ---------------------------------------------------------------------------
// Flash attention on mma.sync, cp.async 2-stage, single sync per K/V tile.
// Block: 128 threads (4 warps), 128 q-rows; warp owns 32 q-rows (i=0..1).
// Q fragments loaded directly from gmem into registers (one-time).
// ---------------------------------------------------------------------------
#define ASTR 72   // bf16 per smem row (64 data + 8 pad); 144B stride
#define AARR (64 * ASTR * 2)         // 9216 B per array
#define ASTG (4 * AARR)              // 36864 B per stage
#define ASMEM (2 * ASTG)             // 73728 B total

__global__ __launch_bounds__(128)
void attn_mma_kernel()
{
    extern __shared__ char dsm[];
    const uint32_t sbase = smem_u32(dsm);

    const int bh = blockIdx.y;
    const int q0 = blockIdx.x * 128;
    const int tid = threadIdx.x;
    const int lane = tid & 31, wid = tid >> 5;
    const int j = lane >> 3, r = lane & 7;
    const int gid = lane >> 2, tg2 = (lane & 3) * 2;

    const size_t headoff = (size_t)bh * TT * DH;
    const __nv_bfloat16* pQh = g_qhi + headoff + (size_t)q0 * DH;
    const __nv_bfloat16* pQl = g_qlo + headoff + (size_t)q0 * DH;
    const __nv_bfloat16* pKh = g_khi + headoff;
    const __nv_bfloat16* pKl = g_klo + headoff;
    const __nv_bfloat16* pVh = g_vhi + headoff;
    const __nv_bfloat16* pVl = g_vlo + headoff;

    // K/V tile-load mapping: 2 threads per row, 32 bf16 (64B) each
    const int lrow = tid >> 1, lhalf = (tid & 1) * 32;
    const uint32_t sm_off = lrow * (ASTR * 2) + lhalf * 2;

    auto PF = [&](int itj, int s) {     // K/V tile j0 = itj*64 -> stage s
        uint32_t b = sbase + s * ASTG + sm_off;
        const char* a = (const char*)(pKh + (size_t)(itj * 64 + lrow) * DH + lhalf);
        const char* c = (const char*)(pKl + (size_t)(itj * 64 + lrow) * DH + lhalf);
        const char* d = (const char*)(pVh + (size_t)(itj * 64 + lrow) * DH + lhalf);
        const char* e = (const char*)(pVl + (size_t)(itj * 64 + lrow) * DH + lhalf);
        #pragma unroll
        for (int s2 = 0; s2 < 4; s2++) {
            cp16(b + s2 * 16,            a + s2 * 16);
            cp16(b + AARR + s2 * 16,     c + s2 * 16);
            cp16(b + 2 * AARR + s2 * 16, d + s2 * 16);
            cp16(b + 3 * AARR + s2 * 16, e + s2 * 16);
        }
    };

    PF(0, 0); cp_commit();

    // ---- Q fragments straight from gmem (A-frag layout m16k16) ----
    uint32_t qh[2][4][4], ql[2][4][4];
    #pragma unroll
    for (int i = 0; i < 2; i++) {
        #pragma unroll
        for (int kk = 0; kk < 4; kk++) {
            #pragma unroll
            for (int rg = 0; rg < 4; rg++) {
                int m = wid * 32 + i * 16 + gid + (rg & 1) * 8;
                int kcol = kk * 16 + tg2 + (rg >> 1) * 8;
                qh[i][kk][rg] = *(const uint32_t*)(pQh + (size_t)m * DH + kcol);
                ql[i][kk][rg] = *(const uint32_t*)(pQl + (size_t)m * DH + kcol);
            }
        }
    }

    const int nB = (j >> 1) * 8 + r, kB = (j & 1) * 8;   // K ldsm lanes
    const int vk = lane & 15, vn8 = (lane >> 4) * 8;     // V trans lanes

    float m_r[2][2] = {{-INFINITY, -INFINITY}, {-INFINITY, -INFINITY}};
    float l_r[2][2] = {{0.0f, 0.0f}, {0.0f, 0.0f}};
    float oacc[2][8][4];
    #pragma unroll
    for (int i = 0; i < 2; i++)
        #pragma unroll
        for (int t = 0; t < 8; t++)
            #pragma unroll
            for (int e = 0; e < 4; e++) oacc[i][t][e] = 0.0f;

    for (int it = 0; it < 32; it++) {
        const int cur = it & 1;
        cp_wait0();
        __syncthreads();
        if (it + 1 < 32) { PF(it + 1, cur ^ 1); cp_commit(); }

        const uint32_t bKh = sbase + cur * ASTG;
        const uint32_t bKl = bKh + AARR;
        const uint32_t bVh = bKh + 2 * AARR;
        const uint32_t bVl = bKh + 3 * AARR;

        // ---- S = Q K^T (3 split combos) ----
        float sacc[2][8][4];
        #pragma unroll
        for (int i = 0; i < 2; i++)
            #pragma unroll
            for (int t = 0; t < 8; t++)
                #pragma unroll
                for (int e = 0; e < 4; e++) sacc[i][t][e] = 0.0f;

        #pragma unroll
        for (int kk = 0; kk < 4; kk++) {
            #pragma unroll
            for (int p = 0; p < 4; p++) {
                uint32_t off = (uint32_t)(p * 16 + nB) * (ASTR * 2)
                             + (uint32_t)(kk * 16 + kB) * 2;
                uint32_t kh4[4], kl4[4];
                ldsm_x4(kh4, bKh + off);
                ldsm_x4(kl4, bKl + off);
                #pragma unroll
                for (int i = 0; i < 2; i++) {
                    mma_bf16(sacc[i][2*p],   qh[i][kk], kh4[0], kh4[1]);
                    mma_bf16(sacc[i][2*p+1], qh[i][kk], kh4[2], kh4[3]);
                    mma_bf16(sacc[i][2*p],   qh[i][kk], kl4[0], kl4[1]);
                    mma_bf16(sacc[i][2*p+1], qh[i][kk], kl4[2], kl4[3]);
                    mma_bf16(sacc[i][2*p],   ql[i][kk], kh4[0], kh4[1]);
                    mma_bf16(sacc[i][2*p+1], ql[i][kk], kh4[2], kh4[3]);
                }
            }
        }

        // ---- online softmax per i (rows gid, gid+8 within each m16) ----
        #pragma unroll
        for (int i = 0; i < 2; i++) {
            float mx0 = -INFINITY, mx1 = -INFINITY;
            #pragma unroll
            for (int t = 0; t < 8; t++) {
                mx0 = fmaxf(mx0, fmaxf(sacc[i][t][0], sacc[i][t][1]));
                mx1 = fmaxf(mx1, fmaxf(sacc[i][t][2], sacc[i][t][3]));
            }
            #pragma unroll
            for (int off = 1; off < 4; off <<= 1) {
                mx0 = fmaxf(mx0, __shfl_xor_sync(0xffffffffu, mx0, off));
                mx1 = fmaxf(mx1, __shfl_xor_sync(0xffffffffu, mx1, off));
            }
            float mn0 = fmaxf(m_r[i][0], mx0), mn1 = fmaxf(m_r[i][1], mx1);
            float cr0 = __expf(m_r[i][0] - mn0), cr1 = __expf(m_r[i][1] - mn1);
            float rs0 = 0.0f, rs1 = 0.0f;
            #pragma unroll
            for (int t = 0; t < 8; t++) {
                sacc[i][t][0] = __expf(sacc[i][t][0] - mn0);
                sacc[i][t][1] = __expf(sacc[i][t][1] - mn0);
                sacc[i][t][2] = __expf(sacc[i][t][2] - mn1);
                sacc[i][t][3] = __expf(sacc[i][t][3] - mn1);
                rs0 += sacc[i][t][0] + sacc[i][t][1];
                rs1 += sacc[i][t][2] + sacc[i][t][3];
            }
            #pragma unroll
            for (int off = 1; off < 4; off <<= 1) {
                rs0 += __shfl_xor_sync(0xffffffffu, rs0, off);
                rs1 += __shfl_xor_sync(0xffffffffu, rs1, off);
            }
            l_r[i][0] = l_r[i][0] * cr0 + rs0;  m_r[i][0] = mn0;
            l_r[i][1] = l_r[i][1] * cr1 + rs1;  m_r[i][1] = mn1;
            #pragma unroll
            for (int t = 0; t < 8; t++) {
                oacc[i][t][0] *= cr0;  oacc[i][t][1] *= cr0;
                oacc[i][t][2] *= cr1;  oacc[i][t][3] *= cr1;
            }
        }

        // ---- O += P V (P split in regs, V split via ldmatrix.trans) ----
        #pragma unroll
        for (int kc = 0; kc < 4; kc++) {
            uint32_t phi[2][4], plo[2][4];
            #pragma unroll
            for (int i = 0; i < 2; i++) {
                split2(sacc[i][2*kc][0],   sacc[i][2*kc][1],   phi[i][0], plo[i][0]);
                split2(sacc[i][2*kc][2],   sacc[i][2*kc][3],   phi[i][1], plo[i][1]);
                split2(sacc[i][2*kc+1][0], sacc[i][2*kc+1][1], phi[i][2], plo[i][2]);
                split2(sacc[i][2*kc+1][2], sacc[i][2*kc+1][3], phi[i][3], plo[i][3]);
            }
            #pragma unroll
            for (int p = 0; p < 4; p++) {
                uint32_t off = (uint32_t)(kc * 16 + vk) * (ASTR * 2)
                             + (uint32_t)(p * 16 + vn8) * 2;
                uint32_t vh4[4], vl4[4];
                ldsm_x4_t(vh4, bVh + off);
                ldsm_x4_t(vl4, bVl + off);
                #pragma unroll
                for (int i = 0; i < 2; i++) {
                    mma_bf16(oacc[i][2*p],   phi[i], vh4[0], vh4[1]);
                    mma_bf16(oacc[i][2*p+1], phi[i], vh4[2], vh4[3]);
                    mma_bf16(oacc[i][2*p],   phi[i], vl4[0], vl4[1]);
                    mma_bf16(oacc[i][2*p+1], phi[i], vl4[2], vl4[3]);
                    mma_bf16(oacc[i][2*p],   plo[i], vh4[0], vh4[1]);
                    mma_bf16(oacc[i][2*p+1], plo[i], vh4[2], vh4[3]);
                }
            }
        }
    }

    // ---- epilogue: normalize, split to bf16 hi/lo, write [B,T,D] ----
    const int b_ = bh >> 4, h = bh & 15;
    uint32_t* ahi32 = (uint32_t*)g_ahi;
    uint32_t* alo32 = (uint32_t*)g_alo;

    #pragma unroll
    for (int i = 0; i < 2; i++) {
        const float inv0 = 1.0f / l_r[i][0], inv1 = 1.0f / l_r[i][1];
        const int row0 = q0 + wid * 32 + i * 16 + gid;
        #pragma unroll
        for (int t = 0; t < 8; t++) {
            const int col = h * 64 + t * 8 + tg2;
            uint32_t hv, lv;
            split2(oacc[i][t][0] * inv0, oacc[i][t][1] * inv0, hv, lv);
            size_t e0 = (((size_t)(b_ * TT + row0)) * DM + col) >> 1;
            ahi32[e0] = hv;  alo32[e0] = lv;
            split2(oacc[i][t][2] * inv1, oacc[i][t][3] * inv1, hv, lv);
            size_t e1 = (((size_t)(b_ * TT + row0 + 8)) * DM + col) >> 1;
            ahi32[e1] = hv;  alo32[e1] = lv;
        }
    }
}

// ---------------------------------------------------------------------------
extern "C" void kernel_launch(void* const* d_in, const int* in_sizes, int n_in,
                              void* d_out, int out_size)
{
    const float* x  = (const float*)d_in[0];
    const float* Wq = (const float*)d_in[1];
    const float* bq = (const float*)d_in[2];
    const float* Wk = (const float*)d_in[3];
    const float* bk = (const float*)d_in[4];
    const float* Wv = (const float*)d_in[5];
    const float* bv = (const float*)d_in[6];
    const float* Wo = (const float*)d_in[7];
    const float* bo = (const float*)d_in[8];
    float* out = (float*)d_out;

    cudaFuncSetAttribute(gemm_mma<0>, cudaFuncAttributeMaxDynamicSharedMemorySize, GSMEM);
    cudaFuncSetAttribute(gemm_mma<1>, cudaFuncAttributeMaxDynamicSharedMemorySize, GSMEM);
    cudaFuncSetAttribute(attn_mma_kernel, cudaFuncAttributeMaxDynamicSharedMemorySize, ASMEM);

    __nv_bfloat16 *xhi, *xlo, *ahi, *alo;
    cudaGetSymbolAddress((void**)&xhi, g_xhi);
    cudaGetSymbolAddress((void**)&xlo, g_xlo);
    cudaGetSymbolAddress((void**)&ahi, g_ahi);
    cudaGetSymbolAddress((void**)&alo, g_alo);

    // 0) split x and weights into bf16 hi/lo (vectorized) + trig table
    split2_kernel<<<(BT * DM / 2 + 255) / 256, 256>>>(x, xhi, xlo, BT * DM / 2);
    split_w2_kernel<<<(4 * DM * DM / 2 + 255) / 256, 256>>>(Wq, Wk, Wv, Wo);
    trig_kernel<<<(TT * 32 + 255) / 256, 256>>>();

    // 1) QKV projection with fused RoPE: q,k,v -> bf16 split [B,H,T,Dh]
    dim3 g1(3072 / 128, BT / 128);
    gemm_mma<0><<<g1, 256, GSMEM>>>(xhi, xlo, bq, bk, bv, nullptr);

    // 2) flash attention (mma.sync + cp.async) -> g_ahi/g_alo [B,T,D]
    dim3 g3(TT / 128, BH);
    attn_mma_kernel<<<g3, 128, ASMEM>>>();

    // 3) output projection -> d_out
    dim3 g4(DM / 128, BT / 128);
    gemm_mma<1><<<g4, 256, GSMEM>>>(ahi, alo, bo, nullptr, nullptr, out);
}

// round 14
// speedup vs baseline: 1.3003x; 1.1428x over previous
#include <cuda_runtime.h>
#include <cuda_bf16.h>
#include <cuda_fp16.h>
#include <math.h>
#include <stdint.h>

// Problem constants
#define BB 2
#define TT 2048
#define DM 1024
#define NH 16
#define DH 64
#define BT (BB*TT)          // 4096
#define BH (BB*NH)          // 32

// Scratch (device globals; no allocation allowed)
__device__ float g_cosv[TT * 32];
__device__ float g_sinv[TT * 32];

// bf16 hi/lo split buffers (QKV projection inputs, Q/K attention operands)
__device__ __nv_bfloat16 g_xhi[BT * DM];
__device__ __nv_bfloat16 g_xlo[BT * DM];
__device__ __nv_bfloat16 g_whi[4 * DM * DM];   // Wq,Wk,Wv bf16-split; Wo fp16-split (slot 3)
__device__ __nv_bfloat16 g_wlo[4 * DM * DM];
__device__ __nv_bfloat16 g_qhi[BH * TT * DH];  // roped, scaled by 0.125
__device__ __nv_bfloat16 g_qlo[BH * TT * DH];
__device__ __nv_bfloat16 g_khi[BH * TT * DH];  // roped
__device__ __nv_bfloat16 g_klo[BH * TT * DH];
// fp16 buffers (PV + out-proj path)
__device__ __half g_vhi[BH * TT * DH];         // V fp16 hi/lo split
__device__ __half g_vlo[BH * TT * DH];
__device__ __half g_aout[BT * DM];             // attn output, single fp16 [B,T,D]

// ---------------------------------------------------------------------------
// PTX helpers (plain sm_103 target: ldmatrix + mma.sync + cp.async)
// ---------------------------------------------------------------------------
__device__ __forceinline__ uint32_t smem_u32(const void* p) {
    uint32_t a;
    asm("{ .reg .u64 t; cvta.to.shared.u64 t, %1; cvt.u32.u64 %0, t; }"
        : "=r"(a) : "l"(p));
    return a;
}

__device__ __forceinline__ void ldsm_x4(uint32_t* r, uint32_t addr) {
    asm volatile("ldmatrix.sync.aligned.m8n8.x4.shared.b16 {%0,%1,%2,%3}, [%4];"
                 : "=r"(r[0]), "=r"(r[1]), "=r"(r[2]), "=r"(r[3]) : "r"(addr));
}

__device__ __forceinline__ void ldsm_x4_t(uint32_t* r, uint32_t addr) {
    asm volatile("ldmatrix.sync.aligned.m8n8.x4.trans.shared.b16 {%0,%1,%2,%3}, [%4];"
                 : "=r"(r[0]), "=r"(r[1]), "=r"(r[2]), "=r"(r[3]) : "r"(addr));
}

__device__ __forceinline__ void mma_bf16(float* d, const uint32_t* a,
                                         uint32_t b0, uint32_t b1) {
    asm volatile(
        "mma.sync.aligned.m16n8k16.row.col.f32.bf16.bf16.f32 "
        "{%0,%1,%2,%3}, {%4,%5,%6,%7}, {%8,%9}, {%0,%1,%2,%3};"
        : "+f"(d[0]), "+f"(d[1]), "+f"(d[2]), "+f"(d[3])
        : "r"(a[0]), "r"(a[1]), "r"(a[2]), "r"(a[3]), "r"(b0), "r"(b1));
}

__device__ __forceinline__ void mma_f16(float* d, const uint32_t* a,
                                        uint32_t b0, uint32_t b1) {
    asm volatile(
        "mma.sync.aligned.m16n8k16.row.col.f32.f16.f16.f32 "
        "{%0,%1,%2,%3}, {%4,%5,%6,%7}, {%8,%9}, {%0,%1,%2,%3};"
        : "+f"(d[0]), "+f"(d[1]), "+f"(d[2]), "+f"(d[3])
        : "r"(a[0]), "r"(a[1]), "r"(a[2]), "r"(a[3]), "r"(b0), "r"(b1));
}

__device__ __forceinline__ void cp16(uint32_t s, const void* g) {
    asm volatile("cp.async.cg.shared.global [%0], [%1], 16;" :: "r"(s), "l"(g));
}
__device__ __forceinline__ void cp_commit() {
    asm volatile("cp.async.commit_group;" ::: "memory");
}
__device__ __forceinline__ void cp_wait0() {
    asm volatile("cp.async.wait_group 0;" ::: "memory");
}

__device__ __forceinline__ uint32_t pack_bf16x2(float x, float y) {
    __nv_bfloat162 h = __floats2bfloat162_rn(x, y);
    return *(uint32_t*)&h;
}

__device__ __forceinline__ uint32_t pack_half2f(float x, float y) {
    __half2 h = __floats2half2_rn(x, y);
    return *(uint32_t*)&h;
}

// bf16 hi/lo split of a float pair
__device__ __forceinline__ void split2(float x, float y,
                                       uint32_t& hv, uint32_t& lv) {
    __nv_bfloat16 h0 = __float2bfloat16(x);
    __nv_bfloat16 h1 = __float2bfloat16(y);
    hv = ((uint32_t)*(uint16_t*)&h1 << 16) | *(uint16_t*)&h0;
    lv = pack_bf16x2(x - __bfloat162float(h0), y - __bfloat162float(h1));
}

// fp16 hi/lo split of a float pair
__device__ __forceinline__ void split2h(float x, float y,
                                        uint32_t& hv, uint32_t& lv) {
    __half h0 = __float2half_rn(x);
    __half h1 = __float2half_rn(y);
    hv = ((uint32_t)__half_as_ushort(h1) << 16) | __half_as_ushort(h0);
    lv = pack_half2f(x - __half2float(h0), y - __half2float(h1));
}

// ---------------------------------------------------------------------------
// fp32 -> split kernels
// ---------------------------------------------------------------------------
__global__ __launch_bounds__(256)
void split2_kernel(const float* __restrict__ src,
                   __nv_bfloat16* __restrict__ hi,
                   __nv_bfloat16* __restrict__ lo, int n2)
{
    int idx = blockIdx.x * blockDim.x + threadIdx.x;
    if (idx >= n2) return;
    float2 v = ((const float2*)src)[idx];
    uint32_t hv, lv;
    split2(v.x, v.y, hv, lv);
    ((uint32_t*)hi)[idx] = hv;
    ((uint32_t*)lo)[idx] = lv;
}

__global__ __launch_bounds__(256)
void split_w2_kernel(const float* __restrict__ w0, const float* __restrict__ w1,
                     const float* __restrict__ w2, const float* __restrict__ w3)
{
    int idx = blockIdx.x * blockDim.x + threadIdx.x;   // 0 .. 2M-1 (pairs)
    int e = idx * 2;
    int w = e >> 20;
    int off = e & 0xFFFFF;
    const float* src = (w == 0) ? w0 : (w == 1) ? w1 : (w == 2) ? w2 : w3;
    float2 v = *(const float2*)(src + off);
    uint32_t hv, lv;
    if (w == 3) split2h(v.x, v.y, hv, lv);   // Wo: fp16 split (used by fp16 mma)
    else        split2(v.x, v.y, hv, lv);    // Wq/Wk/Wv: bf16 split
    ((uint32_t*)g_whi)[idx] = hv;
    ((uint32_t*)g_wlo)[idx] = lv;
}

// ---------------------------------------------------------------------------
// RoPE trig table: one FP64 eval per (t,i).
// Matches JAX fp32 rounding: arg = fp32(t)*fp32(inv_freq); trig in double.
// ---------------------------------------------------------------------------
__global__ __launch_bounds__(256)
void trig_kernel()
{
    int idx = blockIdx.x * blockDim.x + threadIdx.x;   // 0 .. TT*32-1
    if (idx >= TT * 32) return;
    int i = idx & 31;
    int t = idx >> 5;
    double e   = -((double)(2 * i) / 64.0) * log(10000.0);
    float invf = (float)exp(e);
    float argf = (float)t * invf;
    double arg = (double)argf;
    g_cosv[idx] = (float)cos(arg);
    g_sinv[idx] = (float)sin(arg);
}

// ---------------------------------------------------------------------------
// QKV GEMM (3-combo split-bf16, R12 config): 256 thr, 8 warps 4(m)x2(n),
// warp 32x64, cp.async 2-stage, single sync per K-chunk.
// w<2 -> fused RoPE epilogue -> bf16 split g_q*/g_k* [B,H,T,Dh]
// w==2 -> V: fp16 split g_vhi/g_vlo
// ---------------------------------------------------------------------------
#define PADK 40   // bf16 per smem row (32 data + 8 pad); 80B stride
#define GARR (128 * PADK * 2)        // 10240 B per array
#define GSTG (4 * GARR)              // 40960 B per stage
#define GSMEM (2 * GSTG)             // 81920 B total

__global__ __launch_bounds__(256, 2)
void gemm_qkv(const __nv_bfloat16* __restrict__ Ahi,
              const __nv_bfloat16* __restrict__ Alo,
              const float* __restrict__ b0, const float* __restrict__ b1,
              const float* __restrict__ b2)
{
    extern __shared__ char dsm[];
    const uint32_t sbase = smem_u32(dsm);

    const int tid = threadIdx.x;
    const int lane = tid & 31, wid = tid >> 5;
    const int m0 = blockIdx.y * 128;
    const int n_base = blockIdx.x * 128;
    const int w = n_base >> 10;
    const int n_loc0 = n_base & 1023;
    const int warp_m = wid >> 1;
    const int warp_n = wid & 1;

    const int lrow = tid >> 1;
    const int lseg = (tid & 1) * 16;
    const __nv_bfloat16* pAh = Ahi + (size_t)(m0 + lrow) * DM + lseg;
    const __nv_bfloat16* pAl = Alo + (size_t)(m0 + lrow) * DM + lseg;
    const __nv_bfloat16* pWh = g_whi + ((size_t)w << 20) + (size_t)(n_loc0 + lrow) * DM + lseg;
    const __nv_bfloat16* pWl = g_wlo + ((size_t)w << 20) + (size_t)(n_loc0 + lrow) * DM + lseg;

    const uint32_t st_off = lrow * (PADK * 2) + lseg * 2;

    const int j = lane >> 3, r = lane & 7;
    const int mA = (j & 1) * 8 + r;
    const int kA = (j >> 1) * 8;
    const int nB = (j >> 1) * 8 + r;
    const int kB = (j & 1) * 8;

    float acc[2][8][4];
    #pragma unroll
    for (int i = 0; i < 2; i++)
        #pragma unroll
        for (int t = 0; t < 8; t++)
            #pragma unroll
            for (int e = 0; e < 4; e++) acc[i][t][e] = 0.0f;

    auto PF = [&](int c, int s) {
        uint32_t b = sbase + s * GSTG + st_off;
        const char* a  = (const char*)(pAh + c * 32);
        const char* l  = (const char*)(pAl + c * 32);
        const char* h  = (const char*)(pWh + c * 32);
        const char* w2 = (const char*)(pWl + c * 32);
        cp16(b,                  a);   cp16(b + 16,              a + 16);
        cp16(b + GARR,           l);   cp16(b + GARR + 16,       l + 16);
        cp16(b + 2 * GARR,       h);   cp16(b + 2 * GARR + 16,   h + 16);
        cp16(b + 3 * GARR,       w2);  cp16(b + 3 * GARR + 16,   w2 + 16);
    };

    PF(0, 0); cp_commit();

    for (int c = 0; c < 32; c++) {
        const int cur = c & 1;
        cp_wait0();
        __syncthreads();
        if (c + 1 < 32) { PF(c + 1, cur ^ 1); cp_commit(); }

        const uint32_t bAh = sbase + cur * GSTG;
        const uint32_t bAl = bAh + GARR;
        const uint32_t bWh = bAh + 2 * GARR;
        const uint32_t bWl = bAh + 3 * GARR;

        #pragma unroll
        for (int kk = 0; kk < 2; kk++) {
            uint32_t ah[2][4], al[2][4];
            #pragma unroll
            for (int i = 0; i < 2; i++) {
                uint32_t roff = (uint32_t)(warp_m * 32 + i * 16 + mA) * (PADK * 2)
                              + (uint32_t)(kk * 16 + kA) * 2;
                ldsm_x4(ah[i], bAh + roff);
                ldsm_x4(al[i], bAl + roff);
            }
            #pragma unroll
            for (int p = 0; p < 4; p++) {
                uint32_t roff = (uint32_t)(warp_n * 64 + p * 16 + nB) * (PADK * 2)
                              + (uint32_t)(kk * 16 + kB) * 2;
                uint32_t wh[4], wl[4];
                ldsm_x4(wh, bWh + roff);
                ldsm_x4(wl, bWl + roff);
                #pragma unroll
                for (int i = 0; i < 2; i++) {
                    mma_bf16(acc[i][2*p],   ah[i], wh[0], wh[1]);
                    mma_bf16(acc[i][2*p+1], ah[i], wh[2], wh[3]);
                    mma_bf16(acc[i][2*p],   ah[i], wl[0], wl[1]);
                    mma_bf16(acc[i][2*p+1], ah[i], wl[2], wl[3]);
                    mma_bf16(acc[i][2*p],   al[i], wh[0], wh[1]);
                    mma_bf16(acc[i][2*p+1], al[i], wh[2], wh[3]);
                }
            }
        }
    }

    const float* bias = (w == 0) ? b0 : (w == 1) ? b1 : b2;
    const int gid = lane >> 2, tig2 = (lane & 3) * 2;

    if (w < 2) {
        // ---- fused RoPE epilogue: acc[i][t] (cols dh) pairs with acc[i][t+4]
        // (cols dh+32), same rows.  q additionally scaled by 1/8. ----
        const float scl = (w == 0) ? 0.125f : 1.0f;
        __nv_bfloat16* dhi = (w == 0) ? g_qhi : g_khi;
        __nv_bfloat16* dlo = (w == 0) ? g_qlo : g_klo;
        const int h = (n_loc0 + warp_n * 64) >> 6;

        #pragma unroll
        for (int i = 0; i < 2; i++) {
            const int mr0 = m0 + warp_m * 32 + i * 16 + gid;
            #pragma unroll
            for (int t = 0; t < 4; t++) {
                const int dh = t * 8 + tig2;
                const int nl1 = n_loc0 + warp_n * 64 + dh;
                const float bx1 = bias[nl1],      by1 = bias[nl1 + 1];
                const float bx2 = bias[nl1 + 32], by2 = bias[nl1 + 33];
                #pragma unroll
                for (int rs = 0; rs < 2; rs++) {
                    const int m_ = mr0 + rs * 8;
                    const int b_ = m_ >> 11, tt = m_ & 2047;
                    const float c0 = g_cosv[tt * 32 + dh];
                    const float s0 = g_sinv[tt * 32 + dh];
                    const float c1 = g_cosv[tt * 32 + dh + 1];
                    const float s1 = g_sinv[tt * 32 + dh + 1];
                    const float q1a = acc[i][t][rs*2+0]   + bx1;
                    const float q1b = acc[i][t][rs*2+1]   + by1;
                    const float q2a = acc[i][t+4][rs*2+0] + bx2;
                    const float q2b = acc[i][t+4][rs*2+1] + by2;
                    const float r1a = (q1a * c0 - q2a * s0) * scl;
                    const float r2a = (q2a * c0 + q1a * s0) * scl;
                    const float r1b = (q1b * c1 - q2b * s1) * scl;
                    const float r2b = (q2b * c1 + q1b * s1) * scl;
                    size_t base = (((size_t)(b_ * NH + h) * TT) + tt) * DH;
                    uint32_t hv, lv;
                    split2(r1a, r1b, hv, lv);
                    *(uint32_t*)&dhi[base + dh]      = hv;
                    *(uint32_t*)&dlo[base + dh]      = lv;
                    split2(r2a, r2b, hv, lv);
                    *(uint32_t*)&dhi[base + dh + 32] = hv;
                    *(uint32_t*)&dlo[base + dh + 32] = lv;
                }
            }
        }
    } else {
        // ---- V: fp16 hi/lo split ----
        #pragma unroll
        for (int i = 0; i < 2; i++) {
            const int mr0 = m0 + warp_m * 32 + i * 16 + gid;
            #pragma unroll
            for (int t = 0; t < 8; t++) {
                const int nl = n_loc0 + warp_n * 64 + t * 8 + tig2;
                const float bx = bias[nl], by = bias[nl + 1];
                float2 v0 = make_float2(acc[i][t][0] + bx, acc[i][t][1] + by);
                float2 v1 = make_float2(acc[i][t][2] + bx, acc[i][t][3] + by);
                const int h = nl >> 6, dh = nl & 63;
                #pragma unroll
                for (int hv_ = 0; hv_ < 2; hv_++) {
                    const int m_ = mr0 + hv_ * 8;
                    const int b_ = m_ >> 11, tt = m_ & 2047;
                    size_t e = (((size_t)(b_ * NH + h) * TT) + tt) * DH + dh;
                    float vx = hv_ ? v1.x : v0.x, vy = hv_ ? v1.y : v0.y;
                    uint32_t hb, lb;
                    split2h(vx, vy, hb, lb);
                    *(uint32_t*)&g_vhi[e] = hb;
                    *(uint32_t*)&g_vlo[e] = lb;
                }
            }
        }
    }
}

// ---------------------------------------------------------------------------
// Output projection: A = g_aout (single fp16), W = Wo fp16 hi/lo (slot 3).
// 2 combos per MMA group (a*wh + a*wl).  3 smem arrays per stage.
// ---------------------------------------------------------------------------
#define OSTG (3 * GARR)              // 30720 B per stage
#define OSMEM (2 * OSTG)             // 61440 B total

__global__ __launch_bounds__(256, 2)
void gemm_out(const float* __restrict__ bias, float* __restrict__ out)
{
    extern __shared__ char dsm[];
    const uint32_t sbase = smem_u32(dsm);

    const int tid = threadIdx.x;
    const int lane = tid & 31, wid = tid >> 5;
    const int m0 = blockIdx.y * 128;
    const int n0 = blockIdx.x * 128;
    const int warp_m = wid >> 1;
    const int warp_n = wid & 1;

    const int lrow = tid >> 1;
    const int lseg = (tid & 1) * 16;
    const __half* pA = g_aout + (size_t)(m0 + lrow) * DM + lseg;
    const __nv_bfloat16* pWh = g_whi + ((size_t)3 << 20) + (size_t)(n0 + lrow) * DM + lseg;
    const __nv_bfloat16* pWl = g_wlo + ((size_t)3 << 20) + (size_t)(n0 + lrow) * DM + lseg;

    const uint32_t st_off = lrow * (PADK * 2) + lseg * 2;

    const int j = lane >> 3, r = lane & 7;
    const int mA = (j & 1) * 8 + r;
    const int kA = (j >> 1) * 8;
    const int nB = (j >> 1) * 8 + r;
    const int kB = (j & 1) * 8;

    float acc[2][8][4];
    #pragma unroll
    for (int i = 0; i < 2; i++)
        #pragma unroll
        for (int t = 0; t < 8; t++)
            #pragma unroll
            for (int e = 0; e < 4; e++) acc[i][t][e] = 0.0f;

    auto PF = [&](int c, int s) {
        uint32_t b = sbase + s * OSTG + st_off;
        const char* a = (const char*)(pA + c * 32);
        const char* h = (const char*)(pWh + c * 32);
        const char* l = (const char*)(pWl + c * 32);
        cp16(b,              a);  cp16(b + 16,            a + 16);
        cp16(b + GARR,       h);  cp16(b + GARR + 16,     h + 16);
        cp16(b + 2 * GARR,   l);  cp16(b + 2 * GARR + 16, l + 16);
    };

    PF(0, 0); cp_commit();

    for (int c = 0; c < 32; c++) {
        const int cur = c & 1;
        cp_wait0();
        __syncthreads();
        if (c + 1 < 32) { PF(c + 1, cur ^ 1); cp_commit(); }

        const uint32_t bA  = sbase + cur * OSTG;
        const uint32_t bWh = bA + GARR;
        const uint32_t bWl = bA + 2 * GARR;

        #pragma unroll
        for (int kk = 0; kk < 2; kk++) {
            uint32_t ah[2][4];
            #pragma unroll
            for (int i = 0; i < 2; i++) {
                uint32_t roff = (uint32_t)(warp_m * 32 + i * 16 + mA) * (PADK * 2)
                              + (uint32_t)(kk * 16 + kA) * 2;
                ldsm_x4(ah[i], bA + roff);
            }
            #pragma unroll
            for (int p = 0; p < 4; p++) {
                uint32_t roff = (uint32_t)(warp_n * 64 + p * 16 + nB) * (PADK * 2)
                              + (uint32_t)(kk * 16 + kB) * 2;
                uint32_t wh[4], wl[4];
                ldsm_x4(wh, bWh + roff);
                ldsm_x4(wl, bWl + roff);
                #pragma unroll
                for (int i = 0; i < 2; i++) {
                    mma_f16(acc[i][2*p],   ah[i], wh[0], wh[1]);
                    mma_f16(acc[i][2*p+1], ah[i], wh[2], wh[3]);
                    mma_f16(acc[i][2*p],   ah[i], wl[0], wl[1]);
                    mma_f16(acc[i][2*p+1], ah[i], wl[2], wl[3]);
                }
            }
        }
    }

    const int gid = lane >> 2, tig2 = (lane & 3) * 2;
    #pragma unroll
    for (int i = 0; i < 2; i++) {
        const int mr0 = m0 + warp_m * 32 + i * 16 + gid;
        #pragma unroll
        for (int t = 0; t < 8; t++) {
            const int nl = n0 + warp_n * 64 + t * 8 + tig2;
            const float bx = bias[nl], by = bias[nl + 1];
            float2 v0 = make_float2(acc[i][t][0] + bx, acc[i][t][1] + by);
            float2 v1 = make_float2(acc[i][t][2] + bx, acc[i][t][3] + by);
            *(float2*)&out[(size_t)mr0 * DM + nl]       = v0;
            *(float2*)&out[(size_t)(mr0 + 8) * DM + nl] = v1;
        }
    }
}

// ---------------------------------------------------------------------------
// Flash attention: S = QK^T 3-combo bf16; PV 2-combo fp16 (P single fp16,
// V fp16 hi/lo).  128 threads (4 warps), 128 q-rows; warp owns 32 rows.
// Output: single fp16 g_aout [B,T,D].
// ---------------------------------------------------------------------------
#define ASTR 72   // 16-bit elems per smem row (64 data + 8 pad); 144B stride
#define AARR (64 * ASTR * 2)         // 9216 B per array
#define ASTG (4 * AARR)              // 36864 B per stage
#define ASMEM (2 * ASTG)             // 73728 B total

__global__ __launch_bounds__(128)
void attn_mma_kernel()
{
    extern __shared__ char dsm[];
    const uint32_t sbase = smem_u32(dsm);

    const int bh = blockIdx.y;
    const int q0 = blockIdx.x * 128;
    const int tid = threadIdx.x;
    const int lane = tid & 31, wid = tid >> 5;
    const int j = lane >> 3, r = lane & 7;
    const int gid = lane >> 2, tg2 = (lane & 3) * 2;

    const size_t headoff = (size_t)bh * TT * DH;
    const __nv_bfloat16* pQh = g_qhi + headoff + (size_t)q0 * DH;
    const __nv_bfloat16* pQl = g_qlo + headoff + (size_t)q0 * DH;
    const __nv_bfloat16* pKh = g_khi + headoff;
    const __nv_bfloat16* pKl = g_klo + headoff;
    const __half* pVh = g_vhi + headoff;
    const __half* pVl = g_vlo + headoff;

    const int lrow = tid >> 1, lhalf = (tid & 1) * 32;
    const uint32_t sm_off = lrow * (ASTR * 2) + lhalf * 2;

    auto PF = [&](int itj, int s) {
        uint32_t b = sbase + s * ASTG + sm_off;
        const char* a = (const char*)(pKh + (size_t)(itj * 64 + lrow) * DH + lhalf);
        const char* c = (const char*)(pKl + (size_t)(itj * 64 + lrow) * DH + lhalf);
        const char* d = (const char*)(pVh + (size_t)(itj * 64 + lrow) * DH + lhalf);
        const char* e = (const char*)(pVl + (size_t)(itj * 64 + lrow) * DH + lhalf);
        #pragma unroll
        for (int s2 = 0; s2 < 4; s2++) {
            cp16(b + s2 * 16,            a + s2 * 16);
            cp16(b + AARR + s2 * 16,     c + s2 * 16);
            cp16(b + 2 * AARR + s2 * 16, d + s2 * 16);
            cp16(b + 3 * AARR + s2 * 16, e + s2 * 16);
        }
    };

    PF(0, 0); cp_commit();

    // Q fragments straight from gmem (A-frag layout m16k16)
    uint32_t qh[2][4][4], ql[2][4][4];
    #pragma unroll
    for (int i = 0; i < 2; i++) {
        #pragma unroll
        for (int kk = 0; kk < 4; kk++) {
            #pragma unroll
            for (int rg = 0; rg < 4; rg++) {
                int m = wid * 32 + i * 16 + gid + (rg & 1) * 8;
                int kcol = kk * 16 + tg2 + (rg >> 1) * 8;
                qh[i][kk][rg] = *(const uint32_t*)(pQh + (size_t)m * DH + kcol);
                ql[i][kk][rg] = *(const uint32_t*)(pQl + (size_t)m * DH + kcol);
            }
        }
    }

    const int nB = (j >> 1) * 8 + r, kB = (j & 1) * 8;   // K ldsm lanes
    const int vk = lane & 15, vn8 = (lane >> 4) * 8;     // V trans lanes

    float m_r[2][2] = {{-INFINITY, -INFINITY}, {-INFINITY, -INFINITY}};
    float l_r[2][2] = {{0.0f, 0.0f}, {0.0f, 0.0f}};
    float oacc[2][8][4];
    #pragma unroll
    for (int i = 0; i < 2; i++)
        #pragma unroll
        for (int t = 0; t < 8; t++)
            #pragma unroll
            for (int e = 0; e < 4; e++) oacc[i][t][e] = 0.0f;

    for (int it = 0; it < 32; it++) {
        const int cur = it & 1;
        cp_wait0();
        __syncthreads();
        if (it + 1 < 32) { PF(it + 1, cur ^ 1); cp_commit(); }

        const uint32_t bKh = sbase + cur * ASTG;
        const uint32_t bKl = bKh + AARR;
        const uint32_t bVh = bKh + 2 * AARR;
        const uint32_t bVl = bKh + 3 * AARR;

        // ---- S = Q K^T (3 split combos, bf16) ----
        float sacc[2][8][4];
        #pragma unroll
        for (int i = 0; i < 2; i++)
            #pragma unroll
            for (int t = 0; t < 8; t++)
                #pragma unroll
                for (int e = 0; e < 4; e++) sacc[i][t][e] = 0.0f;

        #pragma unroll
        for (int kk = 0; kk < 4; kk++) {
            #pragma unroll
            for (int p = 0; p < 4; p++) {
                uint32_t off = (uint32_t)(p * 16 + nB) * (ASTR * 2)
                             + (uint32_t)(kk * 16 + kB) * 2;
                uint32_t kh4[4], kl4[4];
                ldsm_x4(kh4, bKh + off);
                ldsm_x4(kl4, bKl + off);
                #pragma unroll
                for (int i = 0; i < 2; i++) {
                    mma_bf16(sacc[i][2*p],   qh[i][kk], kh4[0], kh4[1]);
                    mma_bf16(sacc[i][2*p+1], qh[i][kk], kh4[2], kh4[3]);
                    mma_bf16(sacc[i][2*p],   qh[i][kk], kl4[0], kl4[1]);
                    mma_bf16(sacc[i][2*p+1], qh[i][kk], kl4[2], kl4[3]);
                    mma_bf16(sacc[i][2*p],   ql[i][kk], kh4[0], kh4[1]);
                    mma_bf16(sacc[i][2*p+1], ql[i][kk], kh4[2], kh4[3]);
                }
            }
        }

        // ---- online softmax ----
        #pragma unroll
        for (int i = 0; i < 2; i++) {
            float mx0 = -INFINITY, mx1 = -INFINITY;
            #pragma unroll
            for (int t = 0; t < 8; t++) {
                mx0 = fmaxf(mx0, fmaxf(sacc[i][t][0], sacc[i][t][1]));
                mx1 = fmaxf(mx1, fmaxf(sacc[i][t][2], sacc[i][t][3]));
            }
            #pragma unroll
            for (int off = 1; off < 4; off <<= 1) {
                mx0 = fmaxf(mx0, __shfl_xor_sync(0xffffffffu, mx0, off));
                mx1 = fmaxf(mx1, __shfl_xor_sync(0xffffffffu, mx1, off));
            }
            float mn0 = fmaxf(m_r[i][0], mx0), mn1 = fmaxf(m_r[i][1], mx1);
            float cr0 = __expf(m_r[i][0] - mn0), cr1 = __expf(m_r[i][1] - mn1);
            float rs0 = 0.0f, rs1 = 0.0f;
            #pragma unroll
            for (int t = 0; t < 8; t++) {
                sacc[i][t][0] = __expf(sacc[i][t][0] - mn0);
                sacc[i][t][1] = __expf(sacc[i][t][1] - mn0);
                sacc[i][t][2] = __expf(sacc[i][t][2] - mn1);
                sacc[i][t][3] = __expf(sacc[i][t][3] - mn1);
                rs0 += sacc[i][t][0] + sacc[i][t][1];
                rs1 += sacc[i][t][2] + sacc[i][t][3];
            }
            #pragma unroll
            for (int off = 1; off < 4; off <<= 1) {
                rs0 += __shfl_xor_sync(0xffffffffu, rs0, off);
                rs1 += __shfl_xor_sync(0xffffffffu, rs1, off);
            }
            l_r[i][0] = l_r[i][0] * cr0 + rs0;  m_r[i][0] = mn0;
            l_r[i][1] = l_r[i][1] * cr1 + rs1;  m_r[i][1] = mn1;
            #pragma unroll
            for (int t = 0; t < 8; t++) {
                oacc[i][t][0] *= cr0;  oacc[i][t][1] *= cr0;
                oacc[i][t][2] *= cr1;  oacc[i][t][3] *= cr1;
            }
        }

        // ---- O += P V (P single fp16, V fp16 hi/lo: 2 combos) ----
        #pragma unroll
        for (int kc = 0; kc < 4; kc++) {
            uint32_t phi[2][4];
            #pragma unroll
            for (int i = 0; i < 2; i++) {
                phi[i][0] = pack_half2f(sacc[i][2*kc][0],   sacc[i][2*kc][1]);
                phi[i][1] = pack_half2f(sacc[i][2*kc][2],   sacc[i][2*kc][3]);
                phi[i][2] = pack_half2f(sacc[i][2*kc+1][0], sacc[i][2*kc+1][1]);
                phi[i][3] = pack_half2f(sacc[i][2*kc+1][2], sacc[i][2*kc+1][3]);
            }
            #pragma unroll
            for (int p = 0; p < 4; p++) {
                uint32_t off = (uint32_t)(kc * 16 + vk) * (ASTR * 2)
                             + (uint32_t)(p * 16 + vn8) * 2;
                uint32_t vh4[4], vl4[4];
                ldsm_x4_t(vh4, bVh + off);
                ldsm_x4_t(vl4, bVl + off);
                #pragma unroll
                for (int i = 0; i < 2; i++) {
                    mma_f16(oacc[i][2*p],   phi[i], vh4[0], vh4[1]);
                    mma_f16(oacc[i][2*p+1], phi[i], vh4[2], vh4[3]);
                    mma_f16(oacc[i][2*p],   phi[i], vl4[0], vl4[1]);
                    mma_f16(oacc[i][2*p+1], phi[i], vl4[2], vl4[3]);
                }
            }
        }
    }

    // ---- epilogue: normalize, single fp16, write [B,T,D] ----
    const int b_ = bh >> 4, h = bh & 15;
    uint32_t* aout32 = (uint32_t*)g_aout;

    #pragma unroll
    for (int i = 0; i < 2; i++) {
        const float inv0 = 1.0f / l_r[i][0], inv1 = 1.0f / l_r[i][1];
        const int row0 = q0 + wid * 32 + i * 16 + gid;
        #pragma unroll
        for (int t = 0; t < 8; t++) {
            const int col = h * 64 + t * 8 + tg2;
            size_t e0 = (((size_t)(b_ * TT + row0)) * DM + col) >> 1;
            aout32[e0] = pack_half2f(oacc[i][t][0] * inv0, oacc[i][t][1] * inv0);
            size_t e1 = (((size_t)(b_ * TT + row0 + 8)) * DM + col) >> 1;
            aout32[e1] = pack_half2f(oacc[i][t][2] * inv1, oacc[i][t][3] * inv1);
        }
    }
}

// ---------------------------------------------------------------------------
extern "C" void kernel_launch(void* const* d_in, const int* in_sizes, int n_in,
                              void* d_out, int out_size)
{
    const float* x  = (const float*)d_in[0];
    const float* Wq = (const float*)d_in[1];
    const float* bq = (const float*)d_in[2];
    const float* Wk = (const float*)d_in[3];
    const float* bk = (const float*)d_in[4];
    const float* Wv = (const float*)d_in[5];
    const float* bv = (const float*)d_in[6];
    const float* Wo = (const float*)d_in[7];
    const float* bo = (const float*)d_in[8];
    float* out = (float*)d_out;

    cudaFuncSetAttribute(gemm_qkv, cudaFuncAttributeMaxDynamicSharedMemorySize, GSMEM);
    cudaFuncSetAttribute(gemm_out, cudaFuncAttributeMaxDynamicSharedMemorySize, OSMEM);
    cudaFuncSetAttribute(attn_mma_kernel, cudaFuncAttributeMaxDynamicSharedMemorySize, ASMEM);

    __nv_bfloat16 *xhi, *xlo;
    cudaGetSymbolAddress((void**)&xhi, g_xhi);
    cudaGetSymbolAddress((void**)&xlo, g_xlo);

    // 0) splits + trig table
    split2_kernel<<<(BT * DM / 2 + 255) / 256, 256>>>(x, xhi, xlo, BT * DM / 2);
    split_w2_kernel<<<(4 * DM * DM / 2 + 255) / 256, 256>>>(Wq, Wk, Wv, Wo);
    trig_kernel<<<(TT * 32 + 255) / 256, 256>>>();

    // 1) QKV projection with fused RoPE: q,k bf16-split; v fp16-split
    dim3 g1(3072 / 128, BT / 128);
    gemm_qkv<<<g1, 256, GSMEM>>>(xhi, xlo, bq, bk, bv);

    // 2) flash attention -> g_aout fp16 [B,T,D]
    dim3 g3(TT / 128, BH);
    attn_mma_kernel<<<g3, 128, ASMEM>>>();

    // 3) output projection (fp16 2-combo) -> d_out
    dim3 g4(DM / 128, BT / 128);
    gemm_out<<<g4, 256, OSMEM>>>(bo, out);
}

// round 16
// speedup vs baseline: 1.8873x; 1.4514x over previous
#include <cuda_runtime.h>
#include <cuda_bf16.h>
#include <cuda_fp16.h>
#include <math.h>
#include <stdint.h>

// Problem constants
#define BB 2
#define TT 2048
#define DM 1024
#define NH 16
#define DH 64
#define BT (BB*TT)          // 4096
#define BH (BB*NH)          // 32

// Scratch (device globals; no allocation allowed)
__device__ float g_cosv[TT * 32];
__device__ float g_sinv[TT * 32];

// fp16 buffers
__device__ __half g_xh[BT * DM];        // x fp16 hi/lo split
__device__ __half g_xl[BT * DM];
__device__ __half g_wh[4 * DM * DM];    // Wq,Wk,Wv single fp16; slot3 = Wo hi
__device__ __half g_wl[DM * DM];        // Wo lo
__device__ __half g_qh[BH * TT * DH];   // roped q, scaled 0.125, fp16 hi/lo
__device__ __half g_ql[BH * TT * DH];
__device__ __half g_kh[BH * TT * DH];   // roped k, single fp16
__device__ __half g_vh[BH * TT * DH];   // v, single fp16
__device__ __half g_aout[BT * DM];      // attn output, single fp16 [B,T,D]

// ---------------------------------------------------------------------------
// PTX helpers (plain sm_103 target: ldmatrix + mma.sync + cp.async)
// ---------------------------------------------------------------------------
__device__ __forceinline__ uint32_t smem_u32(const void* p) {
    uint32_t a;
    asm("{ .reg .u64 t; cvta.to.shared.u64 t, %1; cvt.u32.u64 %0, t; }"
        : "=r"(a) : "l"(p));
    return a;
}

__device__ __forceinline__ void ldsm_x4(uint32_t* r, uint32_t addr) {
    asm volatile("ldmatrix.sync.aligned.m8n8.x4.shared.b16 {%0,%1,%2,%3}, [%4];"
                 : "=r"(r[0]), "=r"(r[1]), "=r"(r[2]), "=r"(r[3]) : "r"(addr));
}

__device__ __forceinline__ void ldsm_x4_t(uint32_t* r, uint32_t addr) {
    asm volatile("ldmatrix.sync.aligned.m8n8.x4.trans.shared.b16 {%0,%1,%2,%3}, [%4];"
                 : "=r"(r[0]), "=r"(r[1]), "=r"(r[2]), "=r"(r[3]) : "r"(addr));
}

__device__ __forceinline__ void mma_f16(float* d, const uint32_t* a,
                                        uint32_t b0, uint32_t b1) {
    asm volatile(
        "mma.sync.aligned.m16n8k16.row.col.f32.f16.f16.f32 "
        "{%0,%1,%2,%3}, {%4,%5,%6,%7}, {%8,%9}, {%0,%1,%2,%3};"
        : "+f"(d[0]), "+f"(d[1]), "+f"(d[2]), "+f"(d[3])
        : "r"(a[0]), "r"(a[1]), "r"(a[2]), "r"(a[3]), "r"(b0), "r"(b1));
}

__device__ __forceinline__ void cp16(uint32_t s, const void* g) {
    asm volatile("cp.async.cg.shared.global [%0], [%1], 16;" :: "r"(s), "l"(g));
}
__device__ __forceinline__ void cp_commit() {
    asm volatile("cp.async.commit_group;" ::: "memory");
}
__device__ __forceinline__ void cp_wait0() {
    asm volatile("cp.async.wait_group 0;" ::: "memory");
}

__device__ __forceinline__ uint32_t pack_half2f(float x, float y) {
    __half2 h = __floats2half2_rn(x, y);
    return *(uint32_t*)&h;
}

// fp16 hi/lo split of a float pair
__device__ __forceinline__ void split2h(float x, float y,
                                        uint32_t& hv, uint32_t& lv) {
    __half h0 = __float2half_rn(x);
    __half h1 = __float2half_rn(y);
    hv = ((uint32_t)__half_as_ushort(h1) << 16) | __half_as_ushort(h0);
    lv = pack_half2f(x - __half2float(h0), y - __half2float(h1));
}

// ---------------------------------------------------------------------------
// fp32 -> fp16 split kernels
// ---------------------------------------------------------------------------
__global__ __launch_bounds__(256)
void split_x_kernel(const float* __restrict__ src, int n2)
{
    int idx = blockIdx.x * blockDim.x + threadIdx.x;
    if (idx >= n2) return;
    float2 v = ((const float2*)src)[idx];
    uint32_t hv, lv;
    split2h(v.x, v.y, hv, lv);
    ((uint32_t*)g_xh)[idx] = hv;
    ((uint32_t*)g_xl)[idx] = lv;
}

__global__ __launch_bounds__(256)
void split_w_kernel(const float* __restrict__ w0, const float* __restrict__ w1,
                    const float* __restrict__ w2, const float* __restrict__ w3)
{
    int idx = blockIdx.x * blockDim.x + threadIdx.x;   // 0 .. 2M-1 (pairs)
    int e = idx * 2;
    int w = e >> 20;
    int off = e & 0xFFFFF;
    const float* src = (w == 0) ? w0 : (w == 1) ? w1 : (w == 2) ? w2 : w3;
    float2 v = *(const float2*)(src + off);
    if (w == 3) {
        uint32_t hv, lv;
        split2h(v.x, v.y, hv, lv);       // Wo: fp16 hi/lo
        ((uint32_t*)g_wh)[idx] = hv;
        ((uint32_t*)g_wl)[off >> 1] = lv;
    } else {
        ((uint32_t*)g_wh)[idx] = pack_half2f(v.x, v.y);  // single fp16
    }
}

// ---------------------------------------------------------------------------
// RoPE trig table: one FP64 eval per (t,i).
// Matches JAX fp32 rounding: arg = fp32(t)*fp32(inv_freq); trig in double.
// ---------------------------------------------------------------------------
__global__ __launch_bounds__(256)
void trig_kernel()
{
    int idx = blockIdx.x * blockDim.x + threadIdx.x;   // 0 .. TT*32-1
    if (idx >= TT * 32) return;
    int i = idx & 31;
    int t = idx >> 5;
    double e   = -((double)(2 * i) / 64.0) * log(10000.0);
    float invf = (float)exp(e);
    float argf = (float)t * invf;
    double arg = (double)argf;
    g_cosv[idx] = (float)cos(arg);
    g_sinv[idx] = (float)sin(arg);
}

// ---------------------------------------------------------------------------
// QKV GEMM, 2-combo fp16: A = x fp16 hi/lo, W = single fp16.
// 256 thr, 8 warps 4(m)x2(n), warp 32x64, cp.async 2-stage, single sync.
// Stage = 3 arrays (Ah, Al, W).
// w<2 -> fused RoPE epilogue: q -> fp16 hi/lo g_qh/g_ql; k -> single g_kh
// w==2 -> V single fp16 g_vh
// ---------------------------------------------------------------------------
#define PADK 40   // 16-bit elems per smem row (32 data + 8 pad); 80B stride
#define GARR (128 * PADK * 2)        // 10240 B per array
#define QSTG (3 * GARR)              // 30720 B per stage
#define QSMEM (2 * QSTG)             // 61440 B total

__global__ __launch_bounds__(256, 2)
void gemm_qkv(const float* __restrict__ b0, const float* __restrict__ b1,
              const float* __restrict__ b2)
{
    extern __shared__ char dsm[];
    const uint32_t sbase = smem_u32(dsm);

    const int tid = threadIdx.x;
    const int lane = tid & 31, wid = tid >> 5;
    const int m0 = blockIdx.y * 128;
    const int n_base = blockIdx.x * 128;
    const int w = n_base >> 10;
    const int n_loc0 = n_base & 1023;
    const int warp_m = wid >> 1;
    const int warp_n = wid & 1;

    const int lrow = tid >> 1;
    const int lseg = (tid & 1) * 16;
    const __half* pAh = g_xh + (size_t)(m0 + lrow) * DM + lseg;
    const __half* pAl = g_xl + (size_t)(m0 + lrow) * DM + lseg;
    const __half* pW  = g_wh + ((size_t)w << 20) + (size_t)(n_loc0 + lrow) * DM + lseg;

    const uint32_t st_off = lrow * (PADK * 2) + lseg * 2;

    const int j = lane >> 3, r = lane & 7;
    const int mA = (j & 1) * 8 + r;
    const int kA = (j >> 1) * 8;
    const int nB = (j >> 1) * 8 + r;
    const int kB = (j & 1) * 8;

    float acc[2][8][4];
    #pragma unroll
    for (int i = 0; i < 2; i++)
        #pragma unroll
        for (int t = 0; t < 8; t++)
            #pragma unroll
            for (int e = 0; e < 4; e++) acc[i][t][e] = 0.0f;

    auto PF = [&](int c, int s) {
        uint32_t b = sbase + s * QSTG + st_off;
        const char* a = (const char*)(pAh + c * 32);
        const char* l = (const char*)(pAl + c * 32);
        const char* h = (const char*)(pW  + c * 32);
        cp16(b,              a);  cp16(b + 16,            a + 16);
        cp16(b + GARR,       l);  cp16(b + GARR + 16,     l + 16);
        cp16(b + 2 * GARR,   h);  cp16(b + 2 * GARR + 16, h + 16);
    };

    PF(0, 0); cp_commit();

    for (int c = 0; c < 32; c++) {
        const int cur = c & 1;
        cp_wait0();
        __syncthreads();
        if (c + 1 < 32) { PF(c + 1, cur ^ 1); cp_commit(); }

        const uint32_t bAh = sbase + cur * QSTG;
        const uint32_t bAl = bAh + GARR;
        const uint32_t bW  = bAh + 2 * GARR;

        #pragma unroll
        for (int kk = 0; kk < 2; kk++) {
            uint32_t ah[2][4], al[2][4];
            #pragma unroll
            for (int i = 0; i < 2; i++) {
                uint32_t roff = (uint32_t)(warp_m * 32 + i * 16 + mA) * (PADK * 2)
                              + (uint32_t)(kk * 16 + kA) * 2;
                ldsm_x4(ah[i], bAh + roff);
                ldsm_x4(al[i], bAl + roff);
            }
            #pragma unroll
            for (int p = 0; p < 4; p++) {
                uint32_t roff = (uint32_t)(warp_n * 64 + p * 16 + nB) * (PADK * 2)
                              + (uint32_t)(kk * 16 + kB) * 2;
                uint32_t wv[4];
                ldsm_x4(wv, bW + roff);
                #pragma unroll
                for (int i = 0; i < 2; i++) {
                    mma_f16(acc[i][2*p],   ah[i], wv[0], wv[1]);
                    mma_f16(acc[i][2*p+1], ah[i], wv[2], wv[3]);
                    mma_f16(acc[i][2*p],   al[i], wv[0], wv[1]);
                    mma_f16(acc[i][2*p+1], al[i], wv[2], wv[3]);
                }
            }
        }
    }

    const float* bias = (w == 0) ? b0 : (w == 1) ? b1 : b2;
    const int gid = lane >> 2, tig2 = (lane & 3) * 2;

    if (w < 2) {
        // ---- fused RoPE epilogue: acc[i][t] (cols dh) pairs with acc[i][t+4]
        // (cols dh+32), same rows.  q additionally scaled by 1/8. ----
        const float scl = (w == 0) ? 0.125f : 1.0f;
        const int h = (n_loc0 + warp_n * 64) >> 6;

        #pragma unroll
        for (int i = 0; i < 2; i++) {
            const int mr0 = m0 + warp_m * 32 + i * 16 + gid;
            #pragma unroll
            for (int t = 0; t < 4; t++) {
                const int dh = t * 8 + tig2;
                const int nl1 = n_loc0 + warp_n * 64 + dh;
                const float bx1 = bias[nl1],      by1 = bias[nl1 + 1];
                const float bx2 = bias[nl1 + 32], by2 = bias[nl1 + 33];
                #pragma unroll
                for (int rs = 0; rs < 2; rs++) {
                    const int m_ = mr0 + rs * 8;
                    const int b_ = m_ >> 11, tt = m_ & 2047;
                    const float c0 = g_cosv[tt * 32 + dh];
                    const float s0 = g_sinv[tt * 32 + dh];
                    const float c1 = g_cosv[tt * 32 + dh + 1];
                    const float s1 = g_sinv[tt * 32 + dh + 1];
                    const float q1a = acc[i][t][rs*2+0]   + bx1;
                    const float q1b = acc[i][t][rs*2+1]   + by1;
                    const float q2a = acc[i][t+4][rs*2+0] + bx2;
                    const float q2b = acc[i][t+4][rs*2+1] + by2;
                    const float r1a = (q1a * c0 - q2a * s0) * scl;
                    const float r2a = (q2a * c0 + q1a * s0) * scl;
                    const float r1b = (q1b * c1 - q2b * s1) * scl;
                    const float r2b = (q2b * c1 + q1b * s1) * scl;
                    size_t base = (((size_t)(b_ * NH + h) * TT) + tt) * DH;
                    if (w == 0) {
                        uint32_t hv, lv;
                        split2h(r1a, r1b, hv, lv);
                        *(uint32_t*)&g_qh[base + dh]      = hv;
                        *(uint32_t*)&g_ql[base + dh]      = lv;
                        split2h(r2a, r2b, hv, lv);
                        *(uint32_t*)&g_qh[base + dh + 32] = hv;
                        *(uint32_t*)&g_ql[base + dh + 32] = lv;
                    } else {
                        *(uint32_t*)&g_kh[base + dh]      = pack_half2f(r1a, r1b);
                        *(uint32_t*)&g_kh[base + dh + 32] = pack_half2f(r2a, r2b);
                    }
                }
            }
        }
    } else {
        // ---- V: single fp16 ----
        #pragma unroll
        for (int i = 0; i < 2; i++) {
            const int mr0 = m0 + warp_m * 32 + i * 16 + gid;
            #pragma unroll
            for (int t = 0; t < 8; t++) {
                const int nl = n_loc0 + warp_n * 64 + t * 8 + tig2;
                const float bx = bias[nl], by = bias[nl + 1];
                const int h = nl >> 6, dh = nl & 63;
                #pragma unroll
                for (int hv_ = 0; hv_ < 2; hv_++) {
                    const int m_ = mr0 + hv_ * 8;
                    const int b_ = m_ >> 11, tt = m_ & 2047;
                    size_t e = (((size_t)(b_ * NH + h) * TT) + tt) * DH + dh;
                    float vx = (hv_ ? acc[i][t][2] : acc[i][t][0]) + bx;
                    float vy = (hv_ ? acc[i][t][3] : acc[i][t][1]) + by;
                    *(uint32_t*)&g_vh[e] = pack_half2f(vx, vy);
                }
            }
        }
    }
}

// ---------------------------------------------------------------------------
// Output projection: A = g_aout (single fp16), W = Wo fp16 hi/lo.
// 2 combos.  3 smem arrays per stage.  (R14-validated structure.)
// ---------------------------------------------------------------------------
#define OSTG (3 * GARR)              // 30720 B per stage
#define OSMEM (2 * OSTG)             // 61440 B total

__global__ __launch_bounds__(256, 2)
void gemm_out(const float* __restrict__ bias, float* __restrict__ out)
{
    extern __shared__ char dsm[];
    const uint32_t sbase = smem_u32(dsm);

    const int tid = threadIdx.x;
    const int lane = tid & 31, wid = tid >> 5;
    const int m0 = blockIdx.y * 128;
    const int n0 = blockIdx.x * 128;
    const int warp_m = wid >> 1;
    const int warp_n = wid & 1;

    const int lrow = tid >> 1;
    const int lseg = (tid & 1) * 16;
    const __half* pA  = g_aout + (size_t)(m0 + lrow) * DM + lseg;
    const __half* pWh = g_wh + ((size_t)3 << 20) + (size_t)(n0 + lrow) * DM + lseg;
    const __half* pWl = g_wl + (size_t)(n0 + lrow) * DM + lseg;

    const uint32_t st_off = lrow * (PADK * 2) + lseg * 2;

    const int j = lane >> 3, r = lane & 7;
    const int mA = (j & 1) * 8 + r;
    const int kA = (j >> 1) * 8;
    const int nB = (j >> 1) * 8 + r;
    const int kB = (j & 1) * 8;

    float acc[2][8][4];
    #pragma unroll
    for (int i = 0; i < 2; i++)
        #pragma unroll
        for (int t = 0; t < 8; t++)
            #pragma unroll
            for (int e = 0; e < 4; e++) acc[i][t][e] = 0.0f;

    auto PF = [&](int c, int s) {
        uint32_t b = sbase + s * OSTG + st_off;
        const char* a = (const char*)(pA + c * 32);
        const char* h = (const char*)(pWh + c * 32);
        const char* l = (const char*)(pWl + c * 32);
        cp16(b,              a);  cp16(b + 16,            a + 16);
        cp16(b + GARR,       h);  cp16(b + GARR + 16,     h + 16);
        cp16(b + 2 * GARR,   l);  cp16(b + 2 * GARR + 16, l + 16);
    };

    PF(0, 0); cp_commit();

    for (int c = 0; c < 32; c++) {
        const int cur = c & 1;
        cp_wait0();
        __syncthreads();
        if (c + 1 < 32) { PF(c + 1, cur ^ 1); cp_commit(); }

        const uint32_t bA  = sbase + cur * OSTG;
        const uint32_t bWh = bA + GARR;
        const uint32_t bWl = bA + 2 * GARR;

        #pragma unroll
        for (int kk = 0; kk < 2; kk++) {
            uint32_t ah[2][4];
            #pragma unroll
            for (int i = 0; i < 2; i++) {
                uint32_t roff = (uint32_t)(warp_m * 32 + i * 16 + mA) * (PADK * 2)
                              + (uint32_t)(kk * 16 + kA) * 2;
                ldsm_x4(ah[i], bA + roff);
            }
            #pragma unroll
            for (int p = 0; p < 4; p++) {
                uint32_t roff = (uint32_t)(warp_n * 64 + p * 16 + nB) * (PADK * 2)
                              + (uint32_t)(kk * 16 + kB) * 2;
                uint32_t wh[4], wl[4];
                ldsm_x4(wh, bWh + roff);
                ldsm_x4(wl, bWl + roff);
                #pragma unroll
                for (int i = 0; i < 2; i++) {
                    mma_f16(acc[i][2*p],   ah[i], wh[0], wh[1]);
                    mma_f16(acc[i][2*p+1], ah[i], wh[2], wh[3]);
                    mma_f16(acc[i][2*p],   ah[i], wl[0], wl[1]);
                    mma_f16(acc[i][2*p+1], ah[i], wl[2], wl[3]);
                }
            }
        }
    }

    const int gid = lane >> 2, tig2 = (lane & 3) * 2;
    #pragma unroll
    for (int i = 0; i < 2; i++) {
        const int mr0 = m0 + warp_m * 32 + i * 16 + gid;
        #pragma unroll
        for (int t = 0; t < 8; t++) {
            const int nl = n0 + warp_n * 64 + t * 8 + tig2;
            const float bx = bias[nl], by = bias[nl + 1];
            float2 v0 = make_float2(acc[i][t][0] + bx, acc[i][t][1] + by);
            float2 v1 = make_float2(acc[i][t][2] + bx, acc[i][t][3] + by);
            *(float2*)&out[(size_t)mr0 * DM + nl]       = v0;
            *(float2*)&out[(size_t)(mr0 + 8) * DM + nl] = v1;
        }
    }
}

// ---------------------------------------------------------------------------
// Flash attention: S = QK^T 2-combo fp16 (Q hi/lo regs, K single);
// PV 1-combo fp16 (P single, V single).  128 threads, 128 q-rows.
// Stage = 2 smem arrays (K, V).  Output: single fp16 g_aout [B,T,D].
// ---------------------------------------------------------------------------
#define ASTR 72   // 16-bit elems per smem row (64 data + 8 pad); 144B stride
#define AARR (64 * ASTR * 2)         // 9216 B per array
#define ASTG (2 * AARR)              // 18432 B per stage
#define ASMEM (2 * ASTG)             // 36864 B total

__global__ __launch_bounds__(128)
void attn_mma_kernel()
{
    extern __shared__ char dsm[];
    const uint32_t sbase = smem_u32(dsm);

    const int bh = blockIdx.y;
    const int q0 = blockIdx.x * 128;
    const int tid = threadIdx.x;
    const int lane = tid & 31, wid = tid >> 5;
    const int j = lane >> 3, r = lane & 7;
    const int gid = lane >> 2, tg2 = (lane & 3) * 2;

    const size_t headoff = (size_t)bh * TT * DH;
    const __half* pQh = g_qh + headoff + (size_t)q0 * DH;
    const __half* pQl = g_ql + headoff + (size_t)q0 * DH;
    const __half* pK  = g_kh + headoff;
    const __half* pV  = g_vh + headoff;

    const int lrow = tid >> 1, lhalf = (tid & 1) * 32;
    const uint32_t sm_off = lrow * (ASTR * 2) + lhalf * 2;

    auto PF = [&](int itj, int s) {
        uint32_t b = sbase + s * ASTG + sm_off;
        const char* a = (const char*)(pK + (size_t)(itj * 64 + lrow) * DH + lhalf);
        const char* d = (const char*)(pV + (size_t)(itj * 64 + lrow) * DH + lhalf);
        #pragma unroll
        for (int s2 = 0; s2 < 4; s2++) {
            cp16(b + s2 * 16,        a + s2 * 16);
            cp16(b + AARR + s2 * 16, d + s2 * 16);
        }
    };

    PF(0, 0); cp_commit();

    // Q fragments straight from gmem (A-frag layout m16k16)
    uint32_t qh[2][4][4], ql[2][4][4];
    #pragma unroll
    for (int i = 0; i < 2; i++) {
        #pragma unroll
        for (int kk = 0; kk < 4; kk++) {
            #pragma unroll
            for (int rg = 0; rg < 4; rg++) {
                int m = wid * 32 + i * 16 + gid + (rg & 1) * 8;
                int kcol = kk * 16 + tg2 + (rg >> 1) * 8;
                qh[i][kk][rg] = *(const uint32_t*)(pQh + (size_t)m * DH + kcol);
                ql[i][kk][rg] = *(const uint32_t*)(pQl + (size_t)m * DH + kcol);
            }
        }
    }

    const int nB = (j >> 1) * 8 + r, kB = (j & 1) * 8;   // K ldsm lanes
    const int vk = lane & 15, vn8 = (lane >> 4) * 8;     // V trans lanes

    float m_r[2][2] = {{-INFINITY, -INFINITY}, {-INFINITY, -INFINITY}};
    float l_r[2][2] = {{0.0f, 0.0f}, {0.0f, 0.0f}};
    float oacc[2][8][4];
    #pragma unroll
    for (int i = 0; i < 2; i++)
        #pragma unroll
        for (int t = 0; t < 8; t++)
            #pragma unroll
            for (int e = 0; e < 4; e++) oacc[i][t][e] = 0.0f;

    for (int it = 0; it < 32; it++) {
        const int cur = it & 1;
        cp_wait0();
        __syncthreads();
        if (it + 1 < 32) { PF(it + 1, cur ^ 1); cp_commit(); }

        const uint32_t bK = sbase + cur * ASTG;
        const uint32_t bV = bK + AARR;

        // ---- S = Q K^T (2 combos: qh, ql vs single-fp16 K) ----
        float sacc[2][8][4];
        #pragma unroll
        for (int i = 0; i < 2; i++)
            #pragma unroll
            for (int t = 0; t < 8; t++)
                #pragma unroll
                for (int e = 0; e < 4; e++) sacc[i][t][e] = 0.0f;

        #pragma unroll
        for (int kk = 0; kk < 4; kk++) {
            #pragma unroll
            for (int p = 0; p < 4; p++) {
                uint32_t off = (uint32_t)(p * 16 + nB) * (ASTR * 2)
                             + (uint32_t)(kk * 16 + kB) * 2;
                uint32_t k4[4];
                ldsm_x4(k4, bK + off);
                #pragma unroll
                for (int i = 0; i < 2; i++) {
                    mma_f16(sacc[i][2*p],   qh[i][kk], k4[0], k4[1]);
                    mma_f16(sacc[i][2*p+1], qh[i][kk], k4[2], k4[3]);
                    mma_f16(sacc[i][2*p],   ql[i][kk], k4[0], k4[1]);
                    mma_f16(sacc[i][2*p+1], ql[i][kk], k4[2], k4[3]);
                }
            }
        }

        // ---- online softmax ----
        #pragma unroll
        for (int i = 0; i < 2; i++) {
            float mx0 = -INFINITY, mx1 = -INFINITY;
            #pragma unroll
            for (int t = 0; t < 8; t++) {
                mx0 = fmaxf(mx0, fmaxf(sacc[i][t][0], sacc[i][t][1]));
                mx1 = fmaxf(mx1, fmaxf(sacc[i][t][2], sacc[i][t][3]));
            }
            #pragma unroll
            for (int off = 1; off < 4; off <<= 1) {
                mx0 = fmaxf(mx0, __shfl_xor_sync(0xffffffffu, mx0, off));
                mx1 = fmaxf(mx1, __shfl_xor_sync(0xffffffffu, mx1, off));
            }
            float mn0 = fmaxf(m_r[i][0], mx0), mn1 = fmaxf(m_r[i][1], mx1);
            float cr0 = __expf(m_r[i][0] - mn0), cr1 = __expf(m_r[i][1] - mn1);
            float rs0 = 0.0f, rs1 = 0.0f;
            #pragma unroll
            for (int t = 0; t < 8; t++) {
                sacc[i][t][0] = __expf(sacc[i][t][0] - mn0);
                sacc[i][t][1] = __expf(sacc[i][t][1] - mn0);
                sacc[i][t][2] = __expf(sacc[i][t][2] - mn1);
                sacc[i][t][3] = __expf(sacc[i][t][3] - mn1);
                rs0 += sacc[i][t][0] + sacc[i][t][1];
                rs1 += sacc[i][t][2] + sacc[i][t][3];
            }
            #pragma unroll
            for (int off = 1; off < 4; off <<= 1) {
                rs0 += __shfl_xor_sync(0xffffffffu, rs0, off);
                rs1 += __shfl_xor_sync(0xffffffffu, rs1, off);
            }
            l_r[i][0] = l_r[i][0] * cr0 + rs0;  m_r[i][0] = mn0;
            l_r[i][1] = l_r[i][1] * cr1 + rs1;  m_r[i][1] = mn1;
            #pragma unroll
            for (int t = 0; t < 8; t++) {
                oacc[i][t][0] *= cr0;  oacc[i][t][1] *= cr0;
                oacc[i][t][2] *= cr1;  oacc[i][t][3] *= cr1;
            }
        }

        // ---- O += P V (both single fp16: 1 combo) ----
        #pragma unroll
        for (int kc = 0; kc < 4; kc++) {
            uint32_t phi[2][4];
            #pragma unroll
            for (int i = 0; i < 2; i++) {
                phi[i][0] = pack_half2f(sacc[i][2*kc][0],   sacc[i][2*kc][1]);
                phi[i][1] = pack_half2f(sacc[i][2*kc][2],   sacc[i][2*kc][3]);
                phi[i][2] = pack_half2f(sacc[i][2*kc+1][0], sacc[i][2*kc+1][1]);
                phi[i][3] = pack_half2f(sacc[i][2*kc+1][2], sacc[i][2*kc+1][3]);
            }
            #pragma unroll
            for (int p = 0; p < 4; p++) {
                uint32_t off = (uint32_t)(kc * 16 + vk) * (ASTR * 2)
                             + (uint32_t)(p * 16 + vn8) * 2;
                uint32_t v4[4];
                ldsm_x4_t(v4, bV + off);
                #pragma unroll
                for (int i = 0; i < 2; i++) {
                    mma_f16(oacc[i][2*p],   phi[i], v4[0], v4[1]);
                    mma_f16(oacc[i][2*p+1], phi[i], v4[2], v4[3]);
                }
            }
        }
    }

    // ---- epilogue: normalize, single fp16, write [B,T,D] ----
    const int b_ = bh >> 4, h = bh & 15;
    uint32_t* aout32 = (uint32_t*)g_aout;

    #pragma unroll
    for (int i = 0; i < 2; i++) {
        const float inv0 = 1.0f / l_r[i][0], inv1 = 1.0f / l_r[i][1];
        const int row0 = q0 + wid * 32 + i * 16 + gid;
        #pragma unroll
        for (int t = 0; t < 8; t++) {
            const int col = h * 64 + t * 8 + tg2;
            size_t e0 = (((size_t)(b_ * TT + row0)) * DM + col) >> 1;
            aout32[e0] = pack_half2f(oacc[i][t][0] * inv0, oacc[i][t][1] * inv0);
            size_t e1 = (((size_t)(b_ * TT + row0 + 8)) * DM + col) >> 1;
            aout32[e1] = pack_half2f(oacc[i][t][2] * inv1, oacc[i][t][3] * inv1);
        }
    }
}

// ---------------------------------------------------------------------------
extern "C" void kernel_launch(void* const* d_in, const int* in_sizes, int n_in,
                              void* d_out, int out_size)
{
    const float* x  = (const float*)d_in[0];
    const float* Wq = (const float*)d_in[1];
    const float* bq = (const float*)d_in[2];
    const float* Wk = (const float*)d_in[3];
    const float* bk = (const float*)d_in[4];
    const float* Wv = (const float*)d_in[5];
    const float* bv = (const float*)d_in[6];
    const float* Wo = (const float*)d_in[7];
    const float* bo = (const float*)d_in[8];
    float* out = (float*)d_out;

    cudaFuncSetAttribute(gemm_qkv, cudaFuncAttributeMaxDynamicSharedMemorySize, QSMEM);
    cudaFuncSetAttribute(gemm_out, cudaFuncAttributeMaxDynamicSharedMemorySize, OSMEM);
    cudaFuncSetAttribute(attn_mma_kernel, cudaFuncAttributeMaxDynamicSharedMemorySize, ASMEM);

    // 0) splits + trig table
    split_x_kernel<<<(BT * DM / 2 + 255) / 256, 256>>>(x, BT * DM / 2);
    split_w_kernel<<<(4 * DM * DM / 2 + 255) / 256, 256>>>(Wq, Wk, Wv, Wo);
    trig_kernel<<<(TT * 32 + 255) / 256, 256>>>();

    // 1) QKV projection (2-combo fp16) with fused RoPE
    dim3 g1(3072 / 128, BT / 128);
    gemm_qkv<<<g1, 256, QSMEM>>>(bq, bk, bv);

    // 2) flash attention (S 2-combo, PV 1-combo) -> g_aout fp16 [B,T,D]
    dim3 g3(TT / 128, BH);
    attn_mma_kernel<<<g3, 128, ASMEM>>>();

    // 3) output projection (fp16 2-combo) -> d_out
    dim3 g4(DM / 128, BT / 128);
    gemm_out<<<g4, 256, OSMEM>>>(bo, out);
}